// round 7
// baseline (speedup 1.0000x reference)
#include <cuda_runtime.h>
#include <cuda_fp16.h>
#include <math.h>
#include <limits.h>

#define NN   50000
#define EE   800000
#define GG   512
#define HH   4
#define CC   64
#define HC   256      // H*C
#define DIN_ 128
#define DENC_ 256

#define MTILES 391          // (NN+127)/128
#define SCAT_BLOCKS 3125    // (EE+255)/256
#define GEMM_BLOCKS (MTILES * 4 * 2)
#define HIST_BLOCKS ((EE + 1023) / 1024)

// ---------------- scratch (static device arrays; no allocation) ----------------
__device__ __half g_xl[NN * HC];     // 25.6 MB (fp16 node features, source)
__device__ __half g_xr[NN * HC];     // 25.6 MB (fp16 node features, target)
__device__ __half g_xh[NN * DIN_];   // 12.8 MB (fp16 input features)
__device__ __half g_whl[DIN_ * HC];  // fp16 weights
__device__ __half g_whr[DIN_ * HC];
__device__ int   g_deg[NN];
__device__ int   g_off[NN + 1];
__device__ int   g_woff[NN];
__device__ int   g_csrc[EE];
__device__ float g_pool[GG * CC];
__device__ int   g_cnt[GG];
__device__ unsigned g_done;

// ---------------- f32x2 packed helpers ----------------
typedef unsigned long long u64;
__device__ __forceinline__ u64 pack2(float x, float y) {
    u64 r; asm("mov.b64 %0, {%1,%2};" : "=l"(r) : "f"(x), "f"(y)); return r;
}
__device__ __forceinline__ void unpack2(u64 v, float& x, float& y) {
    asm("mov.b64 {%0,%1}, %2;" : "=f"(x), "=f"(y) : "l"(v));
}
__device__ __forceinline__ u64 fma2(u64 a, u64 b, u64 c) {
    u64 d; asm("fma.rn.f32x2 %0, %1, %2, %3;" : "=l"(d) : "l"(a), "l"(b), "l"(c));
    return d;
}
__device__ __forceinline__ u64 add2(u64 a, u64 b) {
    u64 d; asm("add.rn.f32x2 %0, %1, %2;" : "=l"(d) : "l"(a), "l"(b)); return d;
}
__device__ __forceinline__ u64 mul2(u64 a, u64 b) {
    u64 d; asm("mul.rn.f32x2 %0, %1, %2;" : "=l"(d) : "l"(a), "l"(b)); return d;
}

// ---------------- mma helpers ----------------
__device__ __forceinline__ unsigned smem_u32(const void* p) {
    return (unsigned)__cvta_generic_to_shared(p);
}
__device__ __forceinline__ void ldm_x4(unsigned& r0, unsigned& r1, unsigned& r2,
                                       unsigned& r3, unsigned addr) {
    asm volatile("ldmatrix.sync.aligned.m8n8.x4.shared.b16 {%0,%1,%2,%3}, [%4];"
                 : "=r"(r0), "=r"(r1), "=r"(r2), "=r"(r3) : "r"(addr));
}
__device__ __forceinline__ void ldm_x4_t(unsigned& r0, unsigned& r1, unsigned& r2,
                                         unsigned& r3, unsigned addr) {
    asm volatile("ldmatrix.sync.aligned.m8n8.x4.trans.shared.b16 {%0,%1,%2,%3}, [%4];"
                 : "=r"(r0), "=r"(r1), "=r"(r2), "=r"(r3) : "r"(addr));
}
__device__ __forceinline__ void mma16816(float* d, const unsigned* a, const unsigned* b) {
    asm volatile(
        "mma.sync.aligned.m16n8k16.row.col.f32.f16.f16.f32 "
        "{%0,%1,%2,%3}, {%4,%5,%6,%7}, {%8,%9}, {%0,%1,%2,%3};"
        : "+f"(d[0]), "+f"(d[1]), "+f"(d[2]), "+f"(d[3])
        : "r"(a[0]), "r"(a[1]), "r"(a[2]), "r"(a[3]), "r"(b[0]), "r"(b[1]));
}

// ---------------- L1: convert to fp16 + zero scratch ----------------
__global__ void k_cvt(const float* __restrict__ x,
                      const float* __restrict__ Wl,
                      const float* __restrict__ Wr) {
    int i = blockIdx.x * blockDim.x + threadIdx.x;
    int stride = gridDim.x * blockDim.x;
    if (i == 0) g_done = 0u;
    for (int j = i; j < NN; j += stride) g_deg[j] = 0;
    for (int j = i; j < GG * CC; j += stride) g_pool[j] = 0.f;
    for (int j = i; j < GG; j += stride) g_cnt[j] = 0;
    for (int j = i; j < NN * DIN_ / 2; j += stride) {
        float2 v = ((const float2*)x)[j];
        ((__half2*)g_xh)[j] = __floats2half2_rn(v.x, v.y);
    }
    for (int j = i; j < DIN_ * HC / 2; j += stride) {
        float2 a = ((const float2*)Wl)[j];
        float2 b = ((const float2*)Wr)[j];
        ((__half2*)g_whl)[j] = __floats2half2_rn(a.x, a.y);
        ((__half2*)g_whr)[j] = __floats2half2_rn(b.x, b.y);
    }
}

// ---------------- L2: histogram + (last block) exclusive scan ----------------
__global__ __launch_bounds__(1024) void k_hist_scan(const int* __restrict__ ei) {
    int t = blockIdx.x * 1024 + threadIdx.x;
    if (t < EE) atomicAdd(&g_deg[ei[EE + t]], 1);

    __threadfence();
    __syncthreads();
    __shared__ bool s_last;
    if (threadIdx.x == 0) {
        unsigned prev = atomicAdd(&g_done, 1u);
        s_last = (prev == (unsigned)(gridDim.x - 1));
    }
    __syncthreads();
    if (!s_last) return;
    __threadfence();

    __shared__ int warpsum[32];
    const int tid = threadIdx.x;
    const int per = (NN + 1023) / 1024;   // 49
    const int base = tid * per;
    int sum = 0;
    for (int i = 0; i < per; i++) {
        int idx = base + i;
        if (idx < NN) sum += g_deg[idx];
    }
    const int lane = tid & 31, wid = tid >> 5;
    int v = sum;
#pragma unroll
    for (int off = 1; off < 32; off <<= 1) {
        int u = __shfl_up_sync(0xffffffffu, v, off);
        if (lane >= off) v += u;
    }
    if (lane == 31) warpsum[wid] = v;
    __syncthreads();
    if (wid == 0) {
        int wv = warpsum[lane];
#pragma unroll
        for (int off = 1; off < 32; off <<= 1) {
            int u = __shfl_up_sync(0xffffffffu, wv, off);
            if (lane >= off) wv += u;
        }
        warpsum[lane] = wv;
    }
    __syncthreads();
    int excl = v - sum + (wid > 0 ? warpsum[wid - 1] : 0);
    int run = excl;
    for (int i = 0; i < per; i++) {
        int idx = base + i;
        if (idx < NN) {
            int c = g_deg[idx];
            g_off[idx] = run;
            g_woff[idx] = run;
            run += c;
        }
    }
    if (tid == 1023) g_off[NN] = run;
}

// ---------------- L3: fused CSR-scatter + tensor-core GEMM ----------------
__global__ __launch_bounds__(256) void k_mid(const float* __restrict__ bl,
                                             const float* __restrict__ br,
                                             const int* __restrict__ ei) {
    __shared__ __half sA[128 * 128];
    __shared__ __half sB[128 * 64];

    const int tid = threadIdx.x;
    int fb = blockIdx.x;

    if (fb < SCAT_BLOCKS) {
        int t = fb * 256 + tid;
        if (t < EE) {
            int dst = ei[EE + t];
            int pos = atomicAdd(&g_woff[dst], 1);
            g_csrc[pos] = ei[t];
        }
        return;
    }
    fb -= SCAT_BLOCKS;
    const int mb = fb % MTILES;
    const int rest = fb / MTILES;
    const int nb = rest & 3;
    const int z = rest >> 2;

    const __half* W   = z ? g_whr : g_whl;
    const float* bias = z ? br : bl;
    __half* out       = z ? g_xr : g_xl;
    const int bm = mb * 128, bn = nb * 64;

#pragma unroll
    for (int it = 0; it < 8; it++) {
        int q = it * 256 + tid;
        int row = q >> 4, cc = q & 15;
        int gm = bm + row;
        uint4 v = make_uint4(0u, 0u, 0u, 0u);
        if (gm < NN) v = *(const uint4*)&g_xh[gm * DIN_ + cc * 8];
        *(uint4*)&sA[row * 128 + ((cc ^ (row & 7)) << 3)] = v;
    }
#pragma unroll
    for (int it = 0; it < 4; it++) {
        int q = it * 256 + tid;
        int row = q >> 3, cc = q & 7;
        uint4 v = *(const uint4*)&W[row * HC + bn + cc * 8];
        *(uint4*)&sB[row * 64 + ((cc ^ (row & 7)) << 3)] = v;
    }
    __syncthreads();

    const int wid = tid >> 5, lane = tid & 31;
    const int wm = (wid & 3) * 32;
    const int wn = (wid >> 2) * 32;

    float acc[2][4][4];
#pragma unroll
    for (int i = 0; i < 2; i++)
#pragma unroll
        for (int j = 0; j < 4; j++)
#pragma unroll
            for (int k = 0; k < 4; k++) acc[i][j][k] = 0.f;

#pragma unroll
    for (int ks = 0; ks < 8; ks++) {
        const int k0 = ks * 16;
        unsigned a[2][4], b[4][2];
#pragma unroll
        for (int am = 0; am < 2; am++) {
            int row = wm + am * 16 + (lane & 15);
            int cc = (k0 >> 3) + (lane >> 4);
            unsigned addr = smem_u32(&sA[row * 128 + ((cc ^ (row & 7)) << 3)]);
            ldm_x4(a[am][0], a[am][1], a[am][2], a[am][3], addr);
        }
#pragma unroll
        for (int bt = 0; bt < 2; bt++) {
            int row = k0 + (lane & 15);
            int cc = ((wn + bt * 16) >> 3) + (lane >> 4);
            unsigned addr = smem_u32(&sB[row * 64 + ((cc ^ (row & 7)) << 3)]);
            unsigned r0, r1, r2, r3;
            ldm_x4_t(r0, r1, r2, r3, addr);
            b[bt * 2 + 0][0] = r0; b[bt * 2 + 0][1] = r1;
            b[bt * 2 + 1][0] = r2; b[bt * 2 + 1][1] = r3;
        }
#pragma unroll
        for (int am = 0; am < 2; am++)
#pragma unroll
            for (int bt = 0; bt < 4; bt++) mma16816(acc[am][bt], a[am], b[bt]);
    }

#pragma unroll
    for (int am = 0; am < 2; am++) {
        int row0 = bm + wm + am * 16 + (lane >> 2);
#pragma unroll
        for (int bt = 0; bt < 4; bt++) {
            int col = bn + wn + bt * 8 + (lane & 3) * 2;
            float b0 = bias[col], b1 = bias[col + 1];
            if (row0 < NN)
                *(__half2*)&out[row0 * HC + col] =
                    __floats2half2_rn(acc[am][bt][0] + b0, acc[am][bt][1] + b1);
            if (row0 + 8 < NN)
                *(__half2*)&out[(row0 + 8) * HC + col] =
                    __floats2half2_rn(acc[am][bt][2] + b0, acc[am][bt][3] + b1);
        }
    }
}

// ---------------- L4 (profiled): fused attention + aggregate + pool ------------
// f32x2 packed math. leaky_0.2(z) = 0.6z + 0.4|z| (abs = 64-bit AND, alu pipe).
__global__ __launch_bounds__(256) void k_node(const float* __restrict__ att,
                                              const float* __restrict__ bgnn,
                                              const int* __restrict__ batch) {
    const int lane = threadIdx.x & 31;
    int w = (blockIdx.x * blockDim.x + threadIdx.x) >> 5;
    const int nw = (gridDim.x * blockDim.x) >> 5;

    u64 at2[4];
    {
        const float4 a0 = *(const float4*)&att[lane * 8 + 0];
        const float4 a1 = *(const float4*)&att[lane * 8 + 4];
        at2[0] = pack2(a0.x, a0.y); at2[1] = pack2(a0.z, a0.w);
        at2[2] = pack2(a1.x, a1.y); at2[3] = pack2(a1.z, a1.w);
    }
    const u64 C06 = pack2(0.6f, 0.6f);
    const u64 C04 = pack2(0.4f, 0.4f);
    const u64 ABSM = 0x7FFFFFFF7FFFFFFFull;

    for (int n = w; n < NN; n += nw) {
        u64 r2[4];
        {
            uint4 ur = *(const uint4*)&g_xr[n * HC + lane * 8];
            float2 f0 = __half22float2(*(__half2*)&ur.x);
            float2 f1 = __half22float2(*(__half2*)&ur.y);
            float2 f2 = __half22float2(*(__half2*)&ur.z);
            float2 f3 = __half22float2(*(__half2*)&ur.w);
            r2[0] = pack2(f0.x, f0.y); r2[1] = pack2(f1.x, f1.y);
            r2[2] = pack2(f2.x, f2.y); r2[3] = pack2(f3.x, f3.y);
        }

        u64 acc2[4] = {0ull, 0ull, 0ull, 0ull};
        float D = 0.f;

        auto doedge = [&](uint4 ul) {
            u64 l2[4];
            {
                float2 f0 = __half22float2(*(__half2*)&ul.x);
                float2 f1 = __half22float2(*(__half2*)&ul.y);
                float2 f2 = __half22float2(*(__half2*)&ul.z);
                float2 f3 = __half22float2(*(__half2*)&ul.w);
                l2[0] = pack2(f0.x, f0.y); l2[1] = pack2(f1.x, f1.y);
                l2[2] = pack2(f2.x, f2.y); l2[3] = pack2(f3.x, f3.y);
            }
            u64 p2 = 0ull;
#pragma unroll
            for (int i = 0; i < 4; i++) {
                u64 z2 = add2(l2[i], r2[i]);
                u64 lk = fma2(z2, C06, mul2(z2 & ABSM, C04));
                p2 = fma2(lk, at2[i], p2);
            }
            float plo, phi;
            unpack2(p2, plo, phi);
            float p = plo + phi;
            p += __shfl_xor_sync(0xffffffffu, p, 4);
            p += __shfl_xor_sync(0xffffffffu, p, 2);
            p += __shfl_xor_sync(0xffffffffu, p, 1);
            const float a = __expf(p);
            D += a;
            const u64 a2 = pack2(a, a);
#pragma unroll
            for (int i = 0; i < 4; i++) acc2[i] = fma2(a2, l2[i], acc2[i]);
        };

        // self loop
        doedge(*(const uint4*)&g_xl[n * HC + lane * 8]);

        const int beg = g_off[n], end = g_off[n + 1];
        int e = beg;
        const int end4 = beg + ((end - beg) & ~3);
        for (; e < end4; e += 4) {
            const int s0 = g_csrc[e], s1 = g_csrc[e + 1];
            const int s2 = g_csrc[e + 2], s3 = g_csrc[e + 3];
            uint4 u0 = *(const uint4*)&g_xl[s0 * HC + lane * 8];
            uint4 u1 = *(const uint4*)&g_xl[s1 * HC + lane * 8];
            uint4 u2 = *(const uint4*)&g_xl[s2 * HC + lane * 8];
            uint4 u3 = *(const uint4*)&g_xl[s3 * HC + lane * 8];
            doedge(u0); doedge(u1); doedge(u2); doedge(u3);
        }
        for (; e < end; e++) {
            const int s = g_csrc[e];
            doedge(*(const uint4*)&g_xl[s * HC + lane * 8]);
        }

        const float inv = 1.f / (D + 1e-16f);
        float v[8];
#pragma unroll
        for (int i = 0; i < 4; i++) {
            float a, b;
            unpack2(acc2[i], a, b);
            float t0 = a * inv, t1 = b * inv;
            t0 += __shfl_xor_sync(0xffffffffu, t0, 8);
            t0 += __shfl_xor_sync(0xffffffffu, t0, 16);
            t1 += __shfl_xor_sync(0xffffffffu, t1, 8);
            t1 += __shfl_xor_sync(0xffffffffu, t1, 16);
            v[2 * i] = t0; v[2 * i + 1] = t1;
        }

        if (lane < 8) {
            const int g = batch[n];
            if (lane == 0) atomicAdd(&g_cnt[g], 1);
#pragma unroll
            for (int j = 0; j < 8; j++) {
                const int c = lane * 8 + j;
                float val = fmaf(0.25f, v[j], bgnn[c]);
                val = fmaxf(val, 0.01f * val);
                atomicAdd(&g_pool[g * CC + c], val);
            }
        }
    }
}

// ---------------- L5: final FC ----------------
__global__ __launch_bounds__(256) void k_fc(const float* __restrict__ hy,
                                            const float* __restrict__ Wfc,
                                            const float* __restrict__ bfc,
                                            float* __restrict__ out) {
    const int g = blockIdx.x;
    const int j = threadIdx.x;
    __shared__ float sh[DENC_ + CC];
    sh[j] = hy[g * DENC_ + j];
    if (j < CC) {
        int c = g_cnt[g];
        float cn = c > 0 ? (float)c : 1.f;
        sh[DENC_ + j] = g_pool[g * CC + j] / cn;
    }
    __syncthreads();
    float acc = bfc[j];
#pragma unroll 8
    for (int k = 0; k < DENC_ + CC; k++)
        acc = fmaf(sh[k], Wfc[k * DENC_ + j], acc);
    out[g * DENC_ + j] = acc;
}

// ---------------- launch ----------------
extern "C" void kernel_launch(void* const* d_in, const int* in_sizes, int n_in,
                              void* d_out, int out_size) {
    const float* hy   = (const float*)d_in[0];
    const float* x    = (const float*)d_in[1];
    const int*   ei   = (const int*)d_in[2];
    const int*   batch= (const int*)d_in[3];
    const float* Wl   = (const float*)d_in[4];
    const float* bl   = (const float*)d_in[5];
    const float* Wr   = (const float*)d_in[6];
    const float* br   = (const float*)d_in[7];
    const float* att  = (const float*)d_in[8];
    const float* bgnn = (const float*)d_in[9];
    const float* Wfc  = (const float*)d_in[10];
    const float* bfc  = (const float*)d_in[11];
    float* out = (float*)d_out;

    k_cvt<<<512, 256>>>(x, Wl, Wr);                            // #1
    k_hist_scan<<<HIST_BLOCKS, 1024>>>(ei);                    // #2
    k_mid<<<SCAT_BLOCKS + GEMM_BLOCKS, 256>>>(bl, br, ei);     // #3
    k_node<<<(NN / 8) + 1, 256>>>(att, bgnn, batch);           // #4 (profiled)
    k_fc<<<GG, 256>>>(hy, Wfc, bfc, out);                      // #5
}

// round 8
// speedup vs baseline: 1.1750x; 1.1750x over previous
#include <cuda_runtime.h>
#include <cuda_fp16.h>
#include <math.h>
#include <limits.h>

#define NN   50000
#define EE   800000
#define GG   512
#define HH   4
#define CC   64
#define HC   256      // H*C
#define DIN_ 128
#define DENC_ 256

#define MTILES 391          // (NN+127)/128
#define SCAT_BLOCKS 3125    // (EE+255)/256
#define GEMM_BLOCKS (MTILES * 4 * 2)
#define HIST_BLOCKS ((EE + 1023) / 1024)

// ---------------- scratch (static device arrays; no allocation) ----------------
__device__ __half g_xl[NN * HC];     // 25.6 MB (fp16 node features, source)
__device__ __half g_xr[NN * HC];     // 25.6 MB (fp16 node features, target)
__device__ __half g_xh[NN * DIN_];   // 12.8 MB (fp16 input features)
__device__ __half g_whl[DIN_ * HC];  // fp16 weights
__device__ __half g_whr[DIN_ * HC];
__device__ int   g_deg[NN];
__device__ int   g_off[NN + 1];
__device__ int   g_woff[NN];
__device__ int   g_csrc[EE];
__device__ float g_pool[GG * CC];
__device__ int   g_cnt[GG];
__device__ unsigned g_done;

// ---------------- mma helpers ----------------
__device__ __forceinline__ unsigned smem_u32(const void* p) {
    return (unsigned)__cvta_generic_to_shared(p);
}
__device__ __forceinline__ void ldm_x4(unsigned& r0, unsigned& r1, unsigned& r2,
                                       unsigned& r3, unsigned addr) {
    asm volatile("ldmatrix.sync.aligned.m8n8.x4.shared.b16 {%0,%1,%2,%3}, [%4];"
                 : "=r"(r0), "=r"(r1), "=r"(r2), "=r"(r3) : "r"(addr));
}
__device__ __forceinline__ void ldm_x4_t(unsigned& r0, unsigned& r1, unsigned& r2,
                                         unsigned& r3, unsigned addr) {
    asm volatile("ldmatrix.sync.aligned.m8n8.x4.trans.shared.b16 {%0,%1,%2,%3}, [%4];"
                 : "=r"(r0), "=r"(r1), "=r"(r2), "=r"(r3) : "r"(addr));
}
__device__ __forceinline__ void mma16816(float* d, const unsigned* a, const unsigned* b) {
    asm volatile(
        "mma.sync.aligned.m16n8k16.row.col.f32.f16.f16.f32 "
        "{%0,%1,%2,%3}, {%4,%5,%6,%7}, {%8,%9}, {%0,%1,%2,%3};"
        : "+f"(d[0]), "+f"(d[1]), "+f"(d[2]), "+f"(d[3])
        : "r"(a[0]), "r"(a[1]), "r"(a[2]), "r"(a[3]), "r"(b[0]), "r"(b[1]));
}

// ---------------- L1: convert to fp16 + zero scratch ----------------
__global__ void k_cvt(const float* __restrict__ x,
                      const float* __restrict__ Wl,
                      const float* __restrict__ Wr) {
    int i = blockIdx.x * blockDim.x + threadIdx.x;
    int stride = gridDim.x * blockDim.x;
    if (i == 0) g_done = 0u;
    for (int j = i; j < NN; j += stride) g_deg[j] = 0;
    for (int j = i; j < GG * CC; j += stride) g_pool[j] = 0.f;
    for (int j = i; j < GG; j += stride) g_cnt[j] = 0;
    for (int j = i; j < NN * DIN_ / 2; j += stride) {
        float2 v = ((const float2*)x)[j];
        ((__half2*)g_xh)[j] = __floats2half2_rn(v.x, v.y);
    }
    for (int j = i; j < DIN_ * HC / 2; j += stride) {
        float2 a = ((const float2*)Wl)[j];
        float2 b = ((const float2*)Wr)[j];
        ((__half2*)g_whl)[j] = __floats2half2_rn(a.x, a.y);
        ((__half2*)g_whr)[j] = __floats2half2_rn(b.x, b.y);
    }
}

// ---------------- L2: histogram + (last block) exclusive scan ----------------
__global__ __launch_bounds__(1024) void k_hist_scan(const int* __restrict__ ei) {
    int t = blockIdx.x * 1024 + threadIdx.x;
    if (t < EE) atomicAdd(&g_deg[ei[EE + t]], 1);

    __threadfence();
    __syncthreads();
    __shared__ bool s_last;
    if (threadIdx.x == 0) {
        unsigned prev = atomicAdd(&g_done, 1u);
        s_last = (prev == (unsigned)(gridDim.x - 1));
    }
    __syncthreads();
    if (!s_last) return;
    __threadfence();

    __shared__ int warpsum[32];
    const int tid = threadIdx.x;
    const int per = (NN + 1023) / 1024;   // 49
    const int base = tid * per;
    int sum = 0;
    for (int i = 0; i < per; i++) {
        int idx = base + i;
        if (idx < NN) sum += g_deg[idx];
    }
    const int lane = tid & 31, wid = tid >> 5;
    int v = sum;
#pragma unroll
    for (int off = 1; off < 32; off <<= 1) {
        int u = __shfl_up_sync(0xffffffffu, v, off);
        if (lane >= off) v += u;
    }
    if (lane == 31) warpsum[wid] = v;
    __syncthreads();
    if (wid == 0) {
        int wv = warpsum[lane];
#pragma unroll
        for (int off = 1; off < 32; off <<= 1) {
            int u = __shfl_up_sync(0xffffffffu, wv, off);
            if (lane >= off) wv += u;
        }
        warpsum[lane] = wv;
    }
    __syncthreads();
    int excl = v - sum + (wid > 0 ? warpsum[wid - 1] : 0);
    int run = excl;
    for (int i = 0; i < per; i++) {
        int idx = base + i;
        if (idx < NN) {
            int c = g_deg[idx];
            g_off[idx] = run;
            g_woff[idx] = run;
            run += c;
        }
    }
    if (tid == 1023) g_off[NN] = run;
}

// ---------------- L3: fused CSR-scatter + tensor-core GEMM ----------------
__global__ __launch_bounds__(256) void k_mid(const float* __restrict__ bl,
                                             const float* __restrict__ br,
                                             const int* __restrict__ ei) {
    __shared__ __half sA[128 * 128];
    __shared__ __half sB[128 * 64];

    const int tid = threadIdx.x;
    int fb = blockIdx.x;

    if (fb < SCAT_BLOCKS) {
        int t = fb * 256 + tid;
        if (t < EE) {
            int dst = ei[EE + t];
            int pos = atomicAdd(&g_woff[dst], 1);
            g_csrc[pos] = ei[t];
        }
        return;
    }
    fb -= SCAT_BLOCKS;
    const int mb = fb % MTILES;
    const int rest = fb / MTILES;
    const int nb = rest & 3;
    const int z = rest >> 2;

    const __half* W   = z ? g_whr : g_whl;
    const float* bias = z ? br : bl;
    __half* out       = z ? g_xr : g_xl;
    const int bm = mb * 128, bn = nb * 64;

#pragma unroll
    for (int it = 0; it < 8; it++) {
        int q = it * 256 + tid;
        int row = q >> 4, cc = q & 15;
        int gm = bm + row;
        uint4 v = make_uint4(0u, 0u, 0u, 0u);
        if (gm < NN) v = *(const uint4*)&g_xh[gm * DIN_ + cc * 8];
        *(uint4*)&sA[row * 128 + ((cc ^ (row & 7)) << 3)] = v;
    }
#pragma unroll
    for (int it = 0; it < 4; it++) {
        int q = it * 256 + tid;
        int row = q >> 3, cc = q & 7;
        uint4 v = *(const uint4*)&W[row * HC + bn + cc * 8];
        *(uint4*)&sB[row * 64 + ((cc ^ (row & 7)) << 3)] = v;
    }
    __syncthreads();

    const int wid = tid >> 5, lane = tid & 31;
    const int wm = (wid & 3) * 32;
    const int wn = (wid >> 2) * 32;

    float acc[2][4][4];
#pragma unroll
    for (int i = 0; i < 2; i++)
#pragma unroll
        for (int j = 0; j < 4; j++)
#pragma unroll
            for (int k = 0; k < 4; k++) acc[i][j][k] = 0.f;

#pragma unroll
    for (int ks = 0; ks < 8; ks++) {
        const int k0 = ks * 16;
        unsigned a[2][4], b[4][2];
#pragma unroll
        for (int am = 0; am < 2; am++) {
            int row = wm + am * 16 + (lane & 15);
            int cc = (k0 >> 3) + (lane >> 4);
            unsigned addr = smem_u32(&sA[row * 128 + ((cc ^ (row & 7)) << 3)]);
            ldm_x4(a[am][0], a[am][1], a[am][2], a[am][3], addr);
        }
#pragma unroll
        for (int bt = 0; bt < 2; bt++) {
            int row = k0 + (lane & 15);
            int cc = ((wn + bt * 16) >> 3) + (lane >> 4);
            unsigned addr = smem_u32(&sB[row * 64 + ((cc ^ (row & 7)) << 3)]);
            unsigned r0, r1, r2, r3;
            ldm_x4_t(r0, r1, r2, r3, addr);
            b[bt * 2 + 0][0] = r0; b[bt * 2 + 0][1] = r1;
            b[bt * 2 + 1][0] = r2; b[bt * 2 + 1][1] = r3;
        }
#pragma unroll
        for (int am = 0; am < 2; am++)
#pragma unroll
            for (int bt = 0; bt < 4; bt++) mma16816(acc[am][bt], a[am], b[bt]);
    }

#pragma unroll
    for (int am = 0; am < 2; am++) {
        int row0 = bm + wm + am * 16 + (lane >> 2);
#pragma unroll
        for (int bt = 0; bt < 4; bt++) {
            int col = bn + wn + bt * 8 + (lane & 3) * 2;
            float b0 = bias[col], b1 = bias[col + 1];
            if (row0 < NN)
                *(__half2*)&out[row0 * HC + col] =
                    __floats2half2_rn(acc[am][bt][0] + b0, acc[am][bt][1] + b1);
            if (row0 + 8 < NN)
                *(__half2*)&out[(row0 + 8) * HC + col] =
                    __floats2half2_rn(acc[am][bt][2] + b0, acc[am][bt][3] + b1);
        }
    }
}

// ---------------- L4 (profiled): fused attention + aggregate + pool ------------
// All per-edge math in native half2 (no conversions): z=hadd2, leaky=hmax2(z,.2z),
// dot=hfma2, accumulate=hfma2 into half2. exp shifted by -6 (cancels in softmax)
// to keep half accumulators far from overflow. Normalization/reductions in fp32.
__global__ __launch_bounds__(128) void k_node(const float* __restrict__ att,
                                              const float* __restrict__ bgnn,
                                              const int* __restrict__ batch) {
    const int lane = threadIdx.x & 31;
    int w = (blockIdx.x * blockDim.x + threadIdx.x) >> 5;
    const int nw = (gridDim.x * blockDim.x) >> 5;

    __half2 at2[4];
    {
        const float4 a0 = *(const float4*)&att[lane * 8 + 0];
        const float4 a1 = *(const float4*)&att[lane * 8 + 4];
        at2[0] = __floats2half2_rn(a0.x, a0.y);
        at2[1] = __floats2half2_rn(a0.z, a0.w);
        at2[2] = __floats2half2_rn(a1.x, a1.y);
        at2[3] = __floats2half2_rn(a1.z, a1.w);
    }
    const __half2 C02 = __float2half2_rn(0.2f);

    for (int n = w; n < NN; n += nw) {
        __half2 r2[4];
        {
            uint4 ur = *(const uint4*)&g_xr[n * HC + lane * 8];
            const __half2* rh = (const __half2*)&ur;
            r2[0] = rh[0]; r2[1] = rh[1]; r2[2] = rh[2]; r2[3] = rh[3];
        }

        __half2 acc2[4];
        acc2[0] = __float2half2_rn(0.f);
        acc2[1] = acc2[0]; acc2[2] = acc2[0]; acc2[3] = acc2[0];
        float D = 0.f;

        auto doedge = [&](uint4 ul) {
            const __half2* lh = (const __half2*)&ul;
            __half2 ps = __float2half2_rn(0.f);
#pragma unroll
            for (int i = 0; i < 4; i++) {
                __half2 z = __hadd2(lh[i], r2[i]);
                __half2 lk = __hmax2(z, __hmul2(z, C02));
                ps = __hfma2(lk, at2[i], ps);
            }
            float2 pf = __half22float2(ps);
            float p = pf.x + pf.y;
            p += __shfl_xor_sync(0xffffffffu, p, 4);
            p += __shfl_xor_sync(0xffffffffu, p, 2);
            p += __shfl_xor_sync(0xffffffffu, p, 1);
            const float a = __expf(p - 6.0f);   // constant shift cancels in softmax
            D += a;
            const __half2 a2 = __float2half2_rn(a);
#pragma unroll
            for (int i = 0; i < 4; i++) acc2[i] = __hfma2(a2, lh[i], acc2[i]);
        };

        // self loop
        doedge(*(const uint4*)&g_xl[n * HC + lane * 8]);

        const int beg = g_off[n], end = g_off[n + 1];
        int e = beg;
        const int end4 = beg + ((end - beg) & ~3);
        for (; e < end4; e += 4) {
            const int s0 = g_csrc[e], s1 = g_csrc[e + 1];
            const int s2 = g_csrc[e + 2], s3 = g_csrc[e + 3];
            uint4 u0 = *(const uint4*)&g_xl[s0 * HC + lane * 8];
            uint4 u1 = *(const uint4*)&g_xl[s1 * HC + lane * 8];
            uint4 u2 = *(const uint4*)&g_xl[s2 * HC + lane * 8];
            uint4 u3 = *(const uint4*)&g_xl[s3 * HC + lane * 8];
            doedge(u0); doedge(u1); doedge(u2); doedge(u3);
        }
        for (; e < end; e++) {
            const int s = g_csrc[e];
            doedge(*(const uint4*)&g_xl[s * HC + lane * 8]);
        }

        const float inv = 1.f / (D + 1e-16f);
        float v[8];
#pragma unroll
        for (int i = 0; i < 4; i++) {
            float2 af = __half22float2(acc2[i]);
            float t0 = af.x * inv, t1 = af.y * inv;
            t0 += __shfl_xor_sync(0xffffffffu, t0, 8);
            t0 += __shfl_xor_sync(0xffffffffu, t0, 16);
            t1 += __shfl_xor_sync(0xffffffffu, t1, 8);
            t1 += __shfl_xor_sync(0xffffffffu, t1, 16);
            v[2 * i] = t0; v[2 * i + 1] = t1;
        }

        if (lane < 8) {
            const int g = batch[n];
            if (lane == 0) atomicAdd(&g_cnt[g], 1);
#pragma unroll
            for (int j = 0; j < 8; j++) {
                const int c = lane * 8 + j;
                float val = fmaf(0.25f, v[j], bgnn[c]);
                val = fmaxf(val, 0.01f * val);
                atomicAdd(&g_pool[g * CC + c], val);
            }
        }
    }
}

// ---------------- L5: final FC ----------------
__global__ __launch_bounds__(256) void k_fc(const float* __restrict__ hy,
                                            const float* __restrict__ Wfc,
                                            const float* __restrict__ bfc,
                                            float* __restrict__ out) {
    const int g = blockIdx.x;
    const int j = threadIdx.x;
    __shared__ float sh[DENC_ + CC];
    sh[j] = hy[g * DENC_ + j];
    if (j < CC) {
        int c = g_cnt[g];
        float cn = c > 0 ? (float)c : 1.f;
        sh[DENC_ + j] = g_pool[g * CC + j] / cn;
    }
    __syncthreads();
    float acc = bfc[j];
#pragma unroll 8
    for (int k = 0; k < DENC_ + CC; k++)
        acc = fmaf(sh[k], Wfc[k * DENC_ + j], acc);
    out[g * DENC_ + j] = acc;
}

// ---------------- launch ----------------
extern "C" void kernel_launch(void* const* d_in, const int* in_sizes, int n_in,
                              void* d_out, int out_size) {
    const float* hy   = (const float*)d_in[0];
    const float* x    = (const float*)d_in[1];
    const int*   ei   = (const int*)d_in[2];
    const int*   batch= (const int*)d_in[3];
    const float* Wl   = (const float*)d_in[4];
    const float* bl   = (const float*)d_in[5];
    const float* Wr   = (const float*)d_in[6];
    const float* br   = (const float*)d_in[7];
    const float* att  = (const float*)d_in[8];
    const float* bgnn = (const float*)d_in[9];
    const float* Wfc  = (const float*)d_in[10];
    const float* bfc  = (const float*)d_in[11];
    float* out = (float*)d_out;

    k_cvt<<<512, 256>>>(x, Wl, Wr);                            // #1
    k_hist_scan<<<HIST_BLOCKS, 1024>>>(ei);                    // #2
    k_mid<<<SCAT_BLOCKS + GEMM_BLOCKS, 256>>>(bl, br, ei);     // #3
    k_node<<<(NN + 3) / 4, 128>>>(att, bgnn, batch);           // #4 (profiled)
    k_fc<<<GG, 256>>>(hy, Wfc, bfc, out);                      // #5
}

// round 9
// speedup vs baseline: 1.2097x; 1.0295x over previous
#include <cuda_runtime.h>
#include <cuda_fp16.h>
#include <math.h>
#include <limits.h>

#define NN   50000
#define EE   800000
#define GG   512
#define HH   4
#define CC   64
#define HC   256      // H*C
#define DIN_ 128
#define DENC_ 256

#define MTILES 391          // (NN+127)/128
#define SCAT_BLOCKS 3125    // (EE+255)/256
#define GEMM_BLOCKS (MTILES * 4 * 2)
#define PRE_BLOCKS 512

// ---------------- scratch (static device arrays; no allocation) ----------------
// INVARIANT: g_deg, g_pool, g_cnt, g_done are ZERO at the start of every
// kernel_launch. Initially true (zero-init); k_fc restores it at the end of
// every launch, so graph replays always see clean scratch.
__device__ __half g_xl[NN * HC];     // 25.6 MB (fp16 node features, source)
__device__ __half g_xr[NN * HC];     // 25.6 MB (fp16 node features, target)
__device__ __half g_xh[NN * DIN_];   // 12.8 MB (fp16 input features)
__device__ __half g_whl[DIN_ * HC];  // fp16 weights
__device__ __half g_whr[DIN_ * HC];
__device__ int   g_deg[NN];
__device__ int   g_off[NN + 1];
__device__ int   g_woff[NN];
__device__ int   g_csrc[EE];
__device__ float g_pool[GG * CC];
__device__ int   g_cnt[GG];
__device__ unsigned g_done;

// ---------------- mma helpers ----------------
__device__ __forceinline__ unsigned smem_u32(const void* p) {
    return (unsigned)__cvta_generic_to_shared(p);
}
__device__ __forceinline__ void ldm_x4(unsigned& r0, unsigned& r1, unsigned& r2,
                                       unsigned& r3, unsigned addr) {
    asm volatile("ldmatrix.sync.aligned.m8n8.x4.shared.b16 {%0,%1,%2,%3}, [%4];"
                 : "=r"(r0), "=r"(r1), "=r"(r2), "=r"(r3) : "r"(addr));
}
__device__ __forceinline__ void ldm_x4_t(unsigned& r0, unsigned& r1, unsigned& r2,
                                         unsigned& r3, unsigned addr) {
    asm volatile("ldmatrix.sync.aligned.m8n8.x4.trans.shared.b16 {%0,%1,%2,%3}, [%4];"
                 : "=r"(r0), "=r"(r1), "=r"(r2), "=r"(r3) : "r"(addr));
}
__device__ __forceinline__ void mma16816(float* d, const unsigned* a, const unsigned* b) {
    asm volatile(
        "mma.sync.aligned.m16n8k16.row.col.f32.f16.f16.f32 "
        "{%0,%1,%2,%3}, {%4,%5,%6,%7}, {%8,%9}, {%0,%1,%2,%3};"
        : "+f"(d[0]), "+f"(d[1]), "+f"(d[2]), "+f"(d[3])
        : "r"(a[0]), "r"(a[1]), "r"(a[2]), "r"(a[3]), "r"(b[0]), "r"(b[1]));
}

// ---------------- L1: fp16 convert + degree histogram + (last block) scan ------
__global__ __launch_bounds__(1024) void k_pre(const float* __restrict__ x,
                                              const float* __restrict__ Wl,
                                              const float* __restrict__ Wr,
                                              const int* __restrict__ ei) {
    const int i = blockIdx.x * 1024 + threadIdx.x;
    const int stride = gridDim.x * 1024;

    for (int j = i; j < NN * DIN_ / 2; j += stride) {
        float2 v = ((const float2*)x)[j];
        ((__half2*)g_xh)[j] = __floats2half2_rn(v.x, v.y);
    }
    for (int j = i; j < DIN_ * HC / 2; j += stride) {
        float2 a = ((const float2*)Wl)[j];
        float2 b = ((const float2*)Wr)[j];
        ((__half2*)g_whl)[j] = __floats2half2_rn(a.x, a.y);
        ((__half2*)g_whr)[j] = __floats2half2_rn(b.x, b.y);
    }
    // histogram (g_deg zeroed by previous launch's k_fc / initial zero-init)
    for (int t = i; t < EE; t += stride) atomicAdd(&g_deg[ei[EE + t]], 1);

    // completion: last block performs the exclusive scan
    __threadfence();
    __syncthreads();
    __shared__ bool s_last;
    if (threadIdx.x == 0) {
        unsigned prev = atomicAdd(&g_done, 1u);
        s_last = (prev == (unsigned)(gridDim.x - 1));
    }
    __syncthreads();
    if (!s_last) return;
    __threadfence();

    __shared__ int warpsum[32];
    const int tid = threadIdx.x;
    const int per = (NN + 1023) / 1024;   // 49
    const int base = tid * per;
    int sum = 0;
    for (int k = 0; k < per; k++) {
        int idx = base + k;
        if (idx < NN) sum += g_deg[idx];
    }
    const int lane = tid & 31, wid = tid >> 5;
    int v = sum;
#pragma unroll
    for (int off = 1; off < 32; off <<= 1) {
        int u = __shfl_up_sync(0xffffffffu, v, off);
        if (lane >= off) v += u;
    }
    if (lane == 31) warpsum[wid] = v;
    __syncthreads();
    if (wid == 0) {
        int wv = warpsum[lane];
#pragma unroll
        for (int off = 1; off < 32; off <<= 1) {
            int u = __shfl_up_sync(0xffffffffu, wv, off);
            if (lane >= off) wv += u;
        }
        warpsum[lane] = wv;
    }
    __syncthreads();
    int excl = v - sum + (wid > 0 ? warpsum[wid - 1] : 0);
    int run = excl;
    for (int k = 0; k < per; k++) {
        int idx = base + k;
        if (idx < NN) {
            int c = g_deg[idx];
            g_off[idx] = run;
            g_woff[idx] = run;
            run += c;
        }
    }
    if (tid == 1023) g_off[NN] = run;
}

// ---------------- L2: fused CSR-scatter + tensor-core GEMM ----------------
__global__ __launch_bounds__(256) void k_mid(const float* __restrict__ bl,
                                             const float* __restrict__ br,
                                             const int* __restrict__ ei) {
    __shared__ __half sA[128 * 128];
    __shared__ __half sB[128 * 64];

    const int tid = threadIdx.x;
    int fb = blockIdx.x;

    if (fb < SCAT_BLOCKS) {
        int t = fb * 256 + tid;
        if (t < EE) {
            int dst = ei[EE + t];
            int pos = atomicAdd(&g_woff[dst], 1);
            g_csrc[pos] = ei[t];
        }
        return;
    }
    fb -= SCAT_BLOCKS;
    const int mb = fb % MTILES;
    const int rest = fb / MTILES;
    const int nb = rest & 3;
    const int z = rest >> 2;

    const __half* W   = z ? g_whr : g_whl;
    const float* bias = z ? br : bl;
    __half* out       = z ? g_xr : g_xl;
    const int bm = mb * 128, bn = nb * 64;

#pragma unroll
    for (int it = 0; it < 8; it++) {
        int q = it * 256 + tid;
        int row = q >> 4, cc = q & 15;
        int gm = bm + row;
        uint4 v = make_uint4(0u, 0u, 0u, 0u);
        if (gm < NN) v = *(const uint4*)&g_xh[gm * DIN_ + cc * 8];
        *(uint4*)&sA[row * 128 + ((cc ^ (row & 7)) << 3)] = v;
    }
#pragma unroll
    for (int it = 0; it < 4; it++) {
        int q = it * 256 + tid;
        int row = q >> 3, cc = q & 7;
        uint4 v = *(const uint4*)&W[row * HC + bn + cc * 8];
        *(uint4*)&sB[row * 64 + ((cc ^ (row & 7)) << 3)] = v;
    }
    __syncthreads();

    const int wid = tid >> 5, lane = tid & 31;
    const int wm = (wid & 3) * 32;
    const int wn = (wid >> 2) * 32;

    float acc[2][4][4];
#pragma unroll
    for (int i = 0; i < 2; i++)
#pragma unroll
        for (int j = 0; j < 4; j++)
#pragma unroll
            for (int k = 0; k < 4; k++) acc[i][j][k] = 0.f;

#pragma unroll
    for (int ks = 0; ks < 8; ks++) {
        const int k0 = ks * 16;
        unsigned a[2][4], b[4][2];
#pragma unroll
        for (int am = 0; am < 2; am++) {
            int row = wm + am * 16 + (lane & 15);
            int cc = (k0 >> 3) + (lane >> 4);
            unsigned addr = smem_u32(&sA[row * 128 + ((cc ^ (row & 7)) << 3)]);
            ldm_x4(a[am][0], a[am][1], a[am][2], a[am][3], addr);
        }
#pragma unroll
        for (int bt = 0; bt < 2; bt++) {
            int row = k0 + (lane & 15);
            int cc = ((wn + bt * 16) >> 3) + (lane >> 4);
            unsigned addr = smem_u32(&sB[row * 64 + ((cc ^ (row & 7)) << 3)]);
            unsigned r0, r1, r2, r3;
            ldm_x4_t(r0, r1, r2, r3, addr);
            b[bt * 2 + 0][0] = r0; b[bt * 2 + 0][1] = r1;
            b[bt * 2 + 1][0] = r2; b[bt * 2 + 1][1] = r3;
        }
#pragma unroll
        for (int am = 0; am < 2; am++)
#pragma unroll
            for (int bt = 0; bt < 4; bt++) mma16816(acc[am][bt], a[am], b[bt]);
    }

#pragma unroll
    for (int am = 0; am < 2; am++) {
        int row0 = bm + wm + am * 16 + (lane >> 2);
#pragma unroll
        for (int bt = 0; bt < 4; bt++) {
            int col = bn + wn + bt * 8 + (lane & 3) * 2;
            float b0 = bias[col], b1 = bias[col + 1];
            if (row0 < NN)
                *(__half2*)&out[row0 * HC + col] =
                    __floats2half2_rn(acc[am][bt][0] + b0, acc[am][bt][1] + b1);
            if (row0 + 8 < NN)
                *(__half2*)&out[(row0 + 8) * HC + col] =
                    __floats2half2_rn(acc[am][bt][2] + b0, acc[am][bt][3] + b1);
        }
    }
}

// ---------------- L3: fused attention + aggregate + pool (half2 math) ----------
__global__ __launch_bounds__(256, 6) void k_node(const float* __restrict__ att,
                                                 const float* __restrict__ bgnn,
                                                 const int* __restrict__ batch) {
    const int lane = threadIdx.x & 31;
    int w = (blockIdx.x * blockDim.x + threadIdx.x) >> 5;
    const int nw = (gridDim.x * blockDim.x) >> 5;

    __half2 at2[4];
    {
        const float4 a0 = *(const float4*)&att[lane * 8 + 0];
        const float4 a1 = *(const float4*)&att[lane * 8 + 4];
        at2[0] = __floats2half2_rn(a0.x, a0.y);
        at2[1] = __floats2half2_rn(a0.z, a0.w);
        at2[2] = __floats2half2_rn(a1.x, a1.y);
        at2[3] = __floats2half2_rn(a1.z, a1.w);
    }
    const __half2 C02 = __float2half2_rn(0.2f);

    for (int n = w; n < NN; n += nw) {
        __half2 r2[4];
        {
            uint4 ur = *(const uint4*)&g_xr[n * HC + lane * 8];
            const __half2* rh = (const __half2*)&ur;
            r2[0] = rh[0]; r2[1] = rh[1]; r2[2] = rh[2]; r2[3] = rh[3];
        }

        __half2 acc2[4];
        acc2[0] = __float2half2_rn(0.f);
        acc2[1] = acc2[0]; acc2[2] = acc2[0]; acc2[3] = acc2[0];
        float D = 0.f;

        auto doedge = [&](uint4 ul) {
            const __half2* lh = (const __half2*)&ul;
            __half2 ps = __float2half2_rn(0.f);
#pragma unroll
            for (int i = 0; i < 4; i++) {
                __half2 z = __hadd2(lh[i], r2[i]);
                __half2 lk = __hmax2(z, __hmul2(z, C02));
                ps = __hfma2(lk, at2[i], ps);
            }
            float2 pf = __half22float2(ps);
            float p = pf.x + pf.y;
            p += __shfl_xor_sync(0xffffffffu, p, 4);
            p += __shfl_xor_sync(0xffffffffu, p, 2);
            p += __shfl_xor_sync(0xffffffffu, p, 1);
            const float a = __expf(p - 6.0f);   // constant shift cancels in softmax
            D += a;
            const __half2 a2 = __float2half2_rn(a);
#pragma unroll
            for (int i = 0; i < 4; i++) acc2[i] = __hfma2(a2, lh[i], acc2[i]);
        };

        // self loop
        doedge(*(const uint4*)&g_xl[n * HC + lane * 8]);

        const int beg = g_off[n], end = g_off[n + 1];
        int e = beg;
        const int end4 = beg + ((end - beg) & ~3);
        for (; e < end4; e += 4) {
            const int s0 = g_csrc[e], s1 = g_csrc[e + 1];
            const int s2 = g_csrc[e + 2], s3 = g_csrc[e + 3];
            uint4 u0 = *(const uint4*)&g_xl[s0 * HC + lane * 8];
            uint4 u1 = *(const uint4*)&g_xl[s1 * HC + lane * 8];
            uint4 u2 = *(const uint4*)&g_xl[s2 * HC + lane * 8];
            uint4 u3 = *(const uint4*)&g_xl[s3 * HC + lane * 8];
            doedge(u0); doedge(u1); doedge(u2); doedge(u3);
        }
        for (; e < end; e++) {
            const int s = g_csrc[e];
            doedge(*(const uint4*)&g_xl[s * HC + lane * 8]);
        }

        const float inv = 1.f / (D + 1e-16f);
        float v[8];
#pragma unroll
        for (int i = 0; i < 4; i++) {
            float2 af = __half22float2(acc2[i]);
            float t0 = af.x * inv, t1 = af.y * inv;
            t0 += __shfl_xor_sync(0xffffffffu, t0, 8);
            t0 += __shfl_xor_sync(0xffffffffu, t0, 16);
            t1 += __shfl_xor_sync(0xffffffffu, t1, 8);
            t1 += __shfl_xor_sync(0xffffffffu, t1, 16);
            v[2 * i] = t0; v[2 * i + 1] = t1;
        }

        if (lane < 8) {
            const int g = batch[n];
            if (lane == 0) atomicAdd(&g_cnt[g], 1);
#pragma unroll
            for (int j = 0; j < 8; j++) {
                const int c = lane * 8 + j;
                float val = fmaf(0.25f, v[j], bgnn[c]);
                val = fmaxf(val, 0.01f * val);
                atomicAdd(&g_pool[g * CC + c], val);
            }
        }
    }
}

// ---------------- L4: final FC + scratch cleanup for next replay ----------------
__global__ __launch_bounds__(256) void k_fc(const float* __restrict__ hy,
                                            const float* __restrict__ Wfc,
                                            const float* __restrict__ bfc,
                                            float* __restrict__ out) {
    const int g = blockIdx.x;
    const int j = threadIdx.x;
    __shared__ float sh[DENC_ + CC];
    sh[j] = hy[g * DENC_ + j];
    if (j < CC) {
        int c = g_cnt[g];
        float cn = c > 0 ? (float)c : 1.f;
        sh[DENC_ + j] = g_pool[g * CC + j] / cn;
    }
    __syncthreads();
    // all g_pool/g_cnt reads for this block are done -> safe to clean up
    if (j < CC) g_pool[g * CC + j] = 0.f;
    if (j == 0) g_cnt[g] = 0;
    for (int t = g * 256 + j; t < NN; t += GG * 256) g_deg[t] = 0;
    if (g == 0 && j == 0) g_done = 0u;

    float acc = bfc[j];
#pragma unroll 8
    for (int k = 0; k < DENC_ + CC; k++)
        acc = fmaf(sh[k], Wfc[k * DENC_ + j], acc);
    out[g * DENC_ + j] = acc;
}

// ---------------- launch ----------------
extern "C" void kernel_launch(void* const* d_in, const int* in_sizes, int n_in,
                              void* d_out, int out_size) {
    const float* hy   = (const float*)d_in[0];
    const float* x    = (const float*)d_in[1];
    const int*   ei   = (const int*)d_in[2];
    const int*   batch= (const int*)d_in[3];
    const float* Wl   = (const float*)d_in[4];
    const float* bl   = (const float*)d_in[5];
    const float* Wr   = (const float*)d_in[6];
    const float* br   = (const float*)d_in[7];
    const float* att  = (const float*)d_in[8];
    const float* bgnn = (const float*)d_in[9];
    const float* Wfc  = (const float*)d_in[10];
    const float* bfc  = (const float*)d_in[11];
    float* out = (float*)d_out;

    k_pre<<<PRE_BLOCKS, 1024>>>(x, Wl, Wr, ei);                // #1 cvt+hist+scan
    k_mid<<<SCAT_BLOCKS + GEMM_BLOCKS, 256>>>(bl, br, ei);     // #2 scatter+gemm
    k_node<<<(NN + 7) / 8, 256>>>(att, bgnn, batch);           // #3
    k_fc<<<GG, 256>>>(hy, Wfc, bfc, out);                      // #4 fc+cleanup
}

// round 10
// speedup vs baseline: 1.2182x; 1.0070x over previous
#include <cuda_runtime.h>
#include <cuda_fp16.h>
#include <math.h>
#include <limits.h>

#define NN   50000
#define EE   800000
#define GG   512
#define HH   4
#define CC   64
#define HC   256      // H*C
#define DIN_ 128
#define DENC_ 256

#define MTILES 391          // (NN+127)/128
#define SCAT_BLOCKS 3125    // (EE+255)/256
#define PRE_BLOCKS 512
#define FC_GPB 4            // graphs per k_fc block
#define FC_BLOCKS (GG / FC_GPB)

// ---------------- scratch (static device arrays; no allocation) ----------------
// INVARIANT: g_deg, g_pool, g_cnt, g_done are ZERO at the start of every
// kernel_launch (zero-init initially; k_fc restores at the end of every launch).
__device__ __half g_xl[NN * HC];     // 25.6 MB (fp16 node features, source)
__device__ __half g_xr[NN * HC];     // 25.6 MB (fp16 node features, target)
__device__ __half g_whl[DIN_ * HC];  // fp16 weights
__device__ __half g_whr[DIN_ * HC];
__device__ int   g_deg[NN];
__device__ int   g_off[NN + 1];
__device__ int   g_woff[NN];
__device__ int   g_csrc[EE];
__device__ float g_pool[GG * CC];
__device__ int   g_cnt[GG];
__device__ unsigned g_done;

// ---------------- mma helpers ----------------
__device__ __forceinline__ unsigned smem_u32(const void* p) {
    return (unsigned)__cvta_generic_to_shared(p);
}
__device__ __forceinline__ void ldm_x4(unsigned& r0, unsigned& r1, unsigned& r2,
                                       unsigned& r3, unsigned addr) {
    asm volatile("ldmatrix.sync.aligned.m8n8.x4.shared.b16 {%0,%1,%2,%3}, [%4];"
                 : "=r"(r0), "=r"(r1), "=r"(r2), "=r"(r3) : "r"(addr));
}
__device__ __forceinline__ void ldm_x4_t(unsigned& r0, unsigned& r1, unsigned& r2,
                                         unsigned& r3, unsigned addr) {
    asm volatile("ldmatrix.sync.aligned.m8n8.x4.trans.shared.b16 {%0,%1,%2,%3}, [%4];"
                 : "=r"(r0), "=r"(r1), "=r"(r2), "=r"(r3) : "r"(addr));
}
__device__ __forceinline__ void mma16816(float* d, const unsigned* a, const unsigned* b) {
    asm volatile(
        "mma.sync.aligned.m16n8k16.row.col.f32.f16.f16.f32 "
        "{%0,%1,%2,%3}, {%4,%5,%6,%7}, {%8,%9}, {%0,%1,%2,%3};"
        : "+f"(d[0]), "+f"(d[1]), "+f"(d[2]), "+f"(d[3])
        : "r"(a[0]), "r"(a[1]), "r"(a[2]), "r"(a[3]), "r"(b[0]), "r"(b[1]));
}

// ---------------- L1: weight fp16 convert + degree histogram + scan ------------
__global__ __launch_bounds__(1024) void k_pre(const float* __restrict__ Wl,
                                              const float* __restrict__ Wr,
                                              const int* __restrict__ ei) {
    const int i = blockIdx.x * 1024 + threadIdx.x;
    const int stride = gridDim.x * 1024;

    for (int j = i; j < DIN_ * HC / 2; j += stride) {
        float2 a = ((const float2*)Wl)[j];
        float2 b = ((const float2*)Wr)[j];
        ((__half2*)g_whl)[j] = __floats2half2_rn(a.x, a.y);
        ((__half2*)g_whr)[j] = __floats2half2_rn(b.x, b.y);
    }
    // histogram (g_deg zero at launch start per invariant)
    for (int t = i; t < EE; t += stride) atomicAdd(&g_deg[ei[EE + t]], 1);

    // last block performs the exclusive scan
    __threadfence();
    __syncthreads();
    __shared__ bool s_last;
    if (threadIdx.x == 0) {
        unsigned prev = atomicAdd(&g_done, 1u);
        s_last = (prev == (unsigned)(gridDim.x - 1));
    }
    __syncthreads();
    if (!s_last) return;
    __threadfence();

    __shared__ int warpsum[32];
    const int tid = threadIdx.x;
    const int per = (NN + 1023) / 1024;   // 49
    const int base = tid * per;
    int sum = 0;
    for (int k = 0; k < per; k++) {
        int idx = base + k;
        if (idx < NN) sum += g_deg[idx];
    }
    const int lane = tid & 31, wid = tid >> 5;
    int v = sum;
#pragma unroll
    for (int off = 1; off < 32; off <<= 1) {
        int u = __shfl_up_sync(0xffffffffu, v, off);
        if (lane >= off) v += u;
    }
    if (lane == 31) warpsum[wid] = v;
    __syncthreads();
    if (wid == 0) {
        int wv = warpsum[lane];
#pragma unroll
        for (int off = 1; off < 32; off <<= 1) {
            int u = __shfl_up_sync(0xffffffffu, wv, off);
            if (lane >= off) wv += u;
        }
        warpsum[lane] = wv;
    }
    __syncthreads();
    int excl = v - sum + (wid > 0 ? warpsum[wid - 1] : 0);
    int run = excl;
    for (int k = 0; k < per; k++) {
        int idx = base + k;
        if (idx < NN) {
            int c = g_deg[idx];
            g_off[idx] = run;
            g_woff[idx] = run;
            run += c;
        }
    }
    if (tid == 1023) g_off[NN] = run;
}

// ---------------- L2: fused CSR-scatter + tensor-core GEMM (A loaded once) ------
// gemm blocks: one per 128-row m-tile. A tile loaded once from fp32 x
// (converted in-flight), then 8 stages (2 weights x 4 n-tiles) stream B.
__global__ __launch_bounds__(256) void k_mid(const float* __restrict__ x,
                                             const float* __restrict__ bl,
                                             const float* __restrict__ br,
                                             const int* __restrict__ ei) {
    __shared__ __half sA[128 * 128];  // 32 KB
    __shared__ __half sB[128 * 64];   // 16 KB

    const int tid = threadIdx.x;
    int fb = blockIdx.x;

    if (fb < SCAT_BLOCKS) {           // ---- scatter part ----
        int t = fb * 256 + tid;
        if (t < EE) {
            int dst = ei[EE + t];
            int pos = atomicAdd(&g_woff[dst], 1);
            g_csrc[pos] = ei[t];
        }
        return;
    }
    const int mb = fb - SCAT_BLOCKS;  // ---- gemm part: m-tile index ----
    const int bm = mb * 128;

    // load A tile once: fp32 -> half, swizzled. 128x128 elems, 16 float4/row.
#pragma unroll
    for (int it = 0; it < 16; it++) {
        int q = it * 256 + tid;
        int row = q >> 5, c4 = q & 31;        // c4: float4 index (4 halves)
        int gm = bm + row;
        float4 v = make_float4(0.f, 0.f, 0.f, 0.f);
        if (gm < NN) v = *(const float4*)&x[gm * DIN_ + c4 * 4];
        __half2 h0 = __floats2half2_rn(v.x, v.y);
        __half2 h1 = __floats2half2_rn(v.z, v.w);
        int cc = c4 >> 1, sub = (c4 & 1) << 2;
        __half* dst = &sA[row * 128 + ((cc ^ (row & 7)) << 3) + sub];
        uint2 pk;
        pk.x = *(unsigned*)&h0; pk.y = *(unsigned*)&h1;
        *(uint2*)dst = pk;
    }

    const int wid = tid >> 5, lane = tid & 31;
    const int wm = (wid & 3) * 32;
    const int wn = (wid >> 2) * 32;

#pragma unroll 1
    for (int stage = 0; stage < 8; stage++) {
        const int z = stage >> 2;
        const int nb = stage & 3;
        const __half* W   = z ? g_whr : g_whl;
        const float* bias = z ? br : bl;
        __half* out       = z ? g_xr : g_xl;
        const int bn = nb * 64;

        __syncthreads();   // sB free (prev stage done); also orders A store once
#pragma unroll
        for (int it = 0; it < 4; it++) {
            int q = it * 256 + tid;
            int row = q >> 3, cc = q & 7;
            uint4 v = *(const uint4*)&W[row * HC + bn + cc * 8];
            *(uint4*)&sB[row * 64 + ((cc ^ (row & 7)) << 3)] = v;
        }
        __syncthreads();

        float acc[2][4][4];
#pragma unroll
        for (int i = 0; i < 2; i++)
#pragma unroll
            for (int j = 0; j < 4; j++)
#pragma unroll
                for (int k = 0; k < 4; k++) acc[i][j][k] = 0.f;

#pragma unroll
        for (int ks = 0; ks < 8; ks++) {
            const int k0 = ks * 16;
            unsigned a[2][4], b[4][2];
#pragma unroll
            for (int am = 0; am < 2; am++) {
                int row = wm + am * 16 + (lane & 15);
                int cc = (k0 >> 3) + (lane >> 4);
                unsigned addr = smem_u32(&sA[row * 128 + ((cc ^ (row & 7)) << 3)]);
                ldm_x4(a[am][0], a[am][1], a[am][2], a[am][3], addr);
            }
#pragma unroll
            for (int bt = 0; bt < 2; bt++) {
                int row = k0 + (lane & 15);
                int cc = ((wn + bt * 16) >> 3) + (lane >> 4);
                unsigned addr = smem_u32(&sB[row * 64 + ((cc ^ (row & 7)) << 3)]);
                unsigned r0, r1, r2, r3;
                ldm_x4_t(r0, r1, r2, r3, addr);
                b[bt * 2 + 0][0] = r0; b[bt * 2 + 0][1] = r1;
                b[bt * 2 + 1][0] = r2; b[bt * 2 + 1][1] = r3;
            }
#pragma unroll
            for (int am = 0; am < 2; am++)
#pragma unroll
                for (int bt = 0; bt < 4; bt++) mma16816(acc[am][bt], a[am], b[bt]);
        }

#pragma unroll
        for (int am = 0; am < 2; am++) {
            int row0 = bm + wm + am * 16 + (lane >> 2);
#pragma unroll
            for (int bt = 0; bt < 4; bt++) {
                int col = bn + wn + bt * 8 + (lane & 3) * 2;
                float b0 = bias[col], b1 = bias[col + 1];
                if (row0 < NN)
                    *(__half2*)&out[row0 * HC + col] =
                        __floats2half2_rn(acc[am][bt][0] + b0, acc[am][bt][1] + b1);
                if (row0 + 8 < NN)
                    *(__half2*)&out[(row0 + 8) * HC + col] =
                        __floats2half2_rn(acc[am][bt][2] + b0, acc[am][bt][3] + b1);
            }
        }
    }
}

// ---------------- L3: fused attention + aggregate + pool (half2 math) ----------
__global__ __launch_bounds__(256, 6) void k_node(const float* __restrict__ att,
                                                 const float* __restrict__ bgnn,
                                                 const int* __restrict__ batch) {
    const int lane = threadIdx.x & 31;
    int w = (blockIdx.x * blockDim.x + threadIdx.x) >> 5;
    const int nw = (gridDim.x * blockDim.x) >> 5;

    __half2 at2[4];
    {
        const float4 a0 = *(const float4*)&att[lane * 8 + 0];
        const float4 a1 = *(const float4*)&att[lane * 8 + 4];
        at2[0] = __floats2half2_rn(a0.x, a0.y);
        at2[1] = __floats2half2_rn(a0.z, a0.w);
        at2[2] = __floats2half2_rn(a1.x, a1.y);
        at2[3] = __floats2half2_rn(a1.z, a1.w);
    }
    const __half2 C02 = __float2half2_rn(0.2f);

    for (int n = w; n < NN; n += nw) {
        __half2 r2[4];
        {
            uint4 ur = *(const uint4*)&g_xr[n * HC + lane * 8];
            const __half2* rh = (const __half2*)&ur;
            r2[0] = rh[0]; r2[1] = rh[1]; r2[2] = rh[2]; r2[3] = rh[3];
        }

        __half2 acc2[4];
        acc2[0] = __float2half2_rn(0.f);
        acc2[1] = acc2[0]; acc2[2] = acc2[0]; acc2[3] = acc2[0];
        float D = 0.f;

        auto doedge = [&](uint4 ul) {
            const __half2* lh = (const __half2*)&ul;
            __half2 ps = __float2half2_rn(0.f);
#pragma unroll
            for (int i = 0; i < 4; i++) {
                __half2 z = __hadd2(lh[i], r2[i]);
                __half2 lk = __hmax2(z, __hmul2(z, C02));
                ps = __hfma2(lk, at2[i], ps);
            }
            float2 pf = __half22float2(ps);
            float p = pf.x + pf.y;
            p += __shfl_xor_sync(0xffffffffu, p, 4);
            p += __shfl_xor_sync(0xffffffffu, p, 2);
            p += __shfl_xor_sync(0xffffffffu, p, 1);
            const float a = __expf(p - 6.0f);   // constant shift cancels in softmax
            D += a;
            const __half2 a2 = __float2half2_rn(a);
#pragma unroll
            for (int i = 0; i < 4; i++) acc2[i] = __hfma2(a2, lh[i], acc2[i]);
        };

        doedge(*(const uint4*)&g_xl[n * HC + lane * 8]);   // self loop

        const int beg = g_off[n], end = g_off[n + 1];
        int e = beg;
        const int end4 = beg + ((end - beg) & ~3);
        for (; e < end4; e += 4) {
            const int s0 = g_csrc[e], s1 = g_csrc[e + 1];
            const int s2 = g_csrc[e + 2], s3 = g_csrc[e + 3];
            uint4 u0 = *(const uint4*)&g_xl[s0 * HC + lane * 8];
            uint4 u1 = *(const uint4*)&g_xl[s1 * HC + lane * 8];
            uint4 u2 = *(const uint4*)&g_xl[s2 * HC + lane * 8];
            uint4 u3 = *(const uint4*)&g_xl[s3 * HC + lane * 8];
            doedge(u0); doedge(u1); doedge(u2); doedge(u3);
        }
        for (; e < end; e++) {
            const int s = g_csrc[e];
            doedge(*(const uint4*)&g_xl[s * HC + lane * 8]);
        }

        const float inv = 1.f / (D + 1e-16f);
        float v[8];
#pragma unroll
        for (int i = 0; i < 4; i++) {
            float2 af = __half22float2(acc2[i]);
            float t0 = af.x * inv, t1 = af.y * inv;
            t0 += __shfl_xor_sync(0xffffffffu, t0, 8);
            t0 += __shfl_xor_sync(0xffffffffu, t0, 16);
            t1 += __shfl_xor_sync(0xffffffffu, t1, 8);
            t1 += __shfl_xor_sync(0xffffffffu, t1, 16);
            v[2 * i] = t0; v[2 * i + 1] = t1;
        }

        if (lane < 8) {
            const int g = batch[n];
            if (lane == 0) atomicAdd(&g_cnt[g], 1);
#pragma unroll
            for (int j = 0; j < 8; j++) {
                const int c = lane * 8 + j;
                float val = fmaf(0.25f, v[j], bgnn[c]);
                val = fmaxf(val, 0.01f * val);
                atomicAdd(&g_pool[g * CC + c], val);
            }
        }
    }
}

// ---------------- L4: final FC (4 graphs/block) + scratch cleanup ---------------
__global__ __launch_bounds__(256) void k_fc(const float* __restrict__ hy,
                                            const float* __restrict__ Wfc,
                                            const float* __restrict__ bfc,
                                            float* __restrict__ out) {
    const int gb = blockIdx.x * FC_GPB;
    const int j = threadIdx.x;
    __shared__ float sh[FC_GPB][DENC_ + CC];

#pragma unroll
    for (int gi = 0; gi < FC_GPB; gi++) {
        const int g = gb + gi;
        sh[gi][j] = hy[g * DENC_ + j];
        if (j < CC) {
            int c = g_cnt[g];
            float cn = c > 0 ? (float)c : 1.f;
            sh[gi][DENC_ + j] = g_pool[g * CC + j] / cn;
        }
    }
    __syncthreads();

    // cleanup for next replay (reads above are done)
#pragma unroll
    for (int gi = 0; gi < FC_GPB; gi++) {
        const int g = gb + gi;
        if (j < CC) g_pool[g * CC + j] = 0.f;
        if (j == 0) g_cnt[g] = 0;
    }
    for (int t = blockIdx.x * 256 + j; t < NN; t += FC_BLOCKS * 256) g_deg[t] = 0;
    if (blockIdx.x == 0 && j == 0) g_done = 0u;

    float acc[FC_GPB];
#pragma unroll
    for (int gi = 0; gi < FC_GPB; gi++) acc[gi] = bfc[j];
#pragma unroll 4
    for (int k = 0; k < DENC_ + CC; k++) {
        const float wv = Wfc[k * DENC_ + j];
#pragma unroll
        for (int gi = 0; gi < FC_GPB; gi++) acc[gi] = fmaf(sh[gi][k], wv, acc[gi]);
    }
#pragma unroll
    for (int gi = 0; gi < FC_GPB; gi++) out[(gb + gi) * DENC_ + j] = acc[gi];
}

// ---------------- launch ----------------
extern "C" void kernel_launch(void* const* d_in, const int* in_sizes, int n_in,
                              void* d_out, int out_size) {
    const float* hy   = (const float*)d_in[0];
    const float* x    = (const float*)d_in[1];
    const int*   ei   = (const int*)d_in[2];
    const int*   batch= (const int*)d_in[3];
    const float* Wl   = (const float*)d_in[4];
    const float* bl   = (const float*)d_in[5];
    const float* Wr   = (const float*)d_in[6];
    const float* br   = (const float*)d_in[7];
    const float* att  = (const float*)d_in[8];
    const float* bgnn = (const float*)d_in[9];
    const float* Wfc  = (const float*)d_in[10];
    const float* bfc  = (const float*)d_in[11];
    float* out = (float*)d_out;

    k_pre<<<PRE_BLOCKS, 1024>>>(Wl, Wr, ei);                   // #1 wcvt+hist+scan
    k_mid<<<SCAT_BLOCKS + MTILES, 256>>>(x, bl, br, ei);       // #2 scatter+gemm
    k_node<<<(NN + 7) / 8, 256>>>(att, bgnn, batch);           // #3
    k_fc<<<FC_BLOCKS, 256>>>(hy, Wfc, bfc, out);               // #4 (profiled)
}

// round 11
// speedup vs baseline: 1.2631x; 1.0368x over previous
#include <cuda_runtime.h>
#include <cuda_fp16.h>
#include <math.h>
#include <limits.h>

#define NN   50000
#define EE   800000
#define GG   512
#define HH   4
#define CC   64
#define HC   256      // H*C
#define DIN_ 128
#define DENC_ 256

#define MTILES 391          // (NN+127)/128
#define SCAT_BLOCKS 3125    // (EE+255)/256
#define PRE_BLOCKS 512
#define FC_GPB 4            // graphs per k_fc block
#define FC_BLOCKS ((GG / FC_GPB) * 2)   // 256: x2 column halves

// ---------------- scratch (static device arrays; no allocation) ----------------
// INVARIANT (replay-safe): g_deg and g_done are zero at the start of every
// kernel_launch (zero-init initially; k_fc restores them at the end).
// g_pool/g_cnt are zeroed by k_pre at the START of each launch (their previous
// values were consumed by the previous launch's k_fc; stream order protects).
__device__ __half g_xl[NN * HC];     // 25.6 MB (fp16 node features, source)
__device__ __half g_xr[NN * HC];     // 25.6 MB (fp16 node features, target)
__device__ __half g_whl[DIN_ * HC];  // fp16 weights
__device__ __half g_whr[DIN_ * HC];
__device__ int   g_deg[NN];
__device__ int   g_off[NN + 1];
__device__ int   g_woff[NN];
__device__ int   g_csrc[EE];
__device__ float g_pool[GG * CC];
__device__ int   g_cnt[GG];
__device__ unsigned g_done;

// ---------------- mma helpers ----------------
__device__ __forceinline__ unsigned smem_u32(const void* p) {
    return (unsigned)__cvta_generic_to_shared(p);
}
__device__ __forceinline__ void ldm_x4(unsigned& r0, unsigned& r1, unsigned& r2,
                                       unsigned& r3, unsigned addr) {
    asm volatile("ldmatrix.sync.aligned.m8n8.x4.shared.b16 {%0,%1,%2,%3}, [%4];"
                 : "=r"(r0), "=r"(r1), "=r"(r2), "=r"(r3) : "r"(addr));
}
__device__ __forceinline__ void ldm_x4_t(unsigned& r0, unsigned& r1, unsigned& r2,
                                         unsigned& r3, unsigned addr) {
    asm volatile("ldmatrix.sync.aligned.m8n8.x4.trans.shared.b16 {%0,%1,%2,%3}, [%4];"
                 : "=r"(r0), "=r"(r1), "=r"(r2), "=r"(r3) : "r"(addr));
}
__device__ __forceinline__ void mma16816(float* d, const unsigned* a, const unsigned* b) {
    asm volatile(
        "mma.sync.aligned.m16n8k16.row.col.f32.f16.f16.f32 "
        "{%0,%1,%2,%3}, {%4,%5,%6,%7}, {%8,%9}, {%0,%1,%2,%3};"
        : "+f"(d[0]), "+f"(d[1]), "+f"(d[2]), "+f"(d[3])
        : "r"(a[0]), "r"(a[1]), "r"(a[2]), "r"(a[3]), "r"(b[0]), "r"(b[1]));
}

// ---------------- L1: weight convert + pool-zero + histogram + scan ------------
__global__ __launch_bounds__(1024) void k_pre(const float* __restrict__ Wl,
                                              const float* __restrict__ Wr,
                                              const int* __restrict__ ei) {
    const int i = blockIdx.x * 1024 + threadIdx.x;
    const int stride = gridDim.x * 1024;

    for (int j = i; j < DIN_ * HC / 2; j += stride) {
        float2 a = ((const float2*)Wl)[j];
        float2 b = ((const float2*)Wr)[j];
        ((__half2*)g_whl)[j] = __floats2half2_rn(a.x, a.y);
        ((__half2*)g_whr)[j] = __floats2half2_rn(b.x, b.y);
    }
    // zero pool/cnt for this launch's k_node (prev launch's k_fc already read them)
    for (int j = i; j < GG * CC; j += stride) g_pool[j] = 0.f;
    for (int j = i; j < GG; j += stride) g_cnt[j] = 0;
    // histogram (g_deg zero at launch start per invariant)
    for (int t = i; t < EE; t += stride) atomicAdd(&g_deg[ei[EE + t]], 1);

    // last block performs the exclusive scan
    __threadfence();
    __syncthreads();
    __shared__ bool s_last;
    if (threadIdx.x == 0) {
        unsigned prev = atomicAdd(&g_done, 1u);
        s_last = (prev == (unsigned)(gridDim.x - 1));
    }
    __syncthreads();
    if (!s_last) return;
    __threadfence();

    __shared__ int warpsum[32];
    const int tid = threadIdx.x;
    const int per = (NN + 1023) / 1024;   // 49
    const int base = tid * per;
    int sum = 0;
    for (int k = 0; k < per; k++) {
        int idx = base + k;
        if (idx < NN) sum += g_deg[idx];
    }
    const int lane = tid & 31, wid = tid >> 5;
    int v = sum;
#pragma unroll
    for (int off = 1; off < 32; off <<= 1) {
        int u = __shfl_up_sync(0xffffffffu, v, off);
        if (lane >= off) v += u;
    }
    if (lane == 31) warpsum[wid] = v;
    __syncthreads();
    if (wid == 0) {
        int wv = warpsum[lane];
#pragma unroll
        for (int off = 1; off < 32; off <<= 1) {
            int u = __shfl_up_sync(0xffffffffu, wv, off);
            if (lane >= off) wv += u;
        }
        warpsum[lane] = wv;
    }
    __syncthreads();
    int excl = v - sum + (wid > 0 ? warpsum[wid - 1] : 0);
    int run = excl;
    for (int k = 0; k < per; k++) {
        int idx = base + k;
        if (idx < NN) {
            int c = g_deg[idx];
            g_off[idx] = run;
            g_woff[idx] = run;
            run += c;
        }
    }
    if (tid == 1023) g_off[NN] = run;
}

// ---------------- L2: fused CSR-scatter + tensor-core GEMM (A loaded once) ------
__global__ __launch_bounds__(256) void k_mid(const float* __restrict__ x,
                                             const float* __restrict__ bl,
                                             const float* __restrict__ br,
                                             const int* __restrict__ ei) {
    __shared__ __half sA[128 * 128];  // 32 KB
    __shared__ __half sB[128 * 64];   // 16 KB

    const int tid = threadIdx.x;
    int fb = blockIdx.x;

    if (fb < SCAT_BLOCKS) {           // ---- scatter part ----
        int t = fb * 256 + tid;
        if (t < EE) {
            int dst = ei[EE + t];
            int pos = atomicAdd(&g_woff[dst], 1);
            g_csrc[pos] = ei[t];
        }
        return;
    }
    const int mb = fb - SCAT_BLOCKS;  // ---- gemm part: m-tile index ----
    const int bm = mb * 128;

    // load A tile once: fp32 -> half, swizzled
#pragma unroll
    for (int it = 0; it < 16; it++) {
        int q = it * 256 + tid;
        int row = q >> 5, c4 = q & 31;
        int gm = bm + row;
        float4 v = make_float4(0.f, 0.f, 0.f, 0.f);
        if (gm < NN) v = *(const float4*)&x[gm * DIN_ + c4 * 4];
        __half2 h0 = __floats2half2_rn(v.x, v.y);
        __half2 h1 = __floats2half2_rn(v.z, v.w);
        int cc = c4 >> 1, sub = (c4 & 1) << 2;
        __half* dst = &sA[row * 128 + ((cc ^ (row & 7)) << 3) + sub];
        uint2 pk;
        pk.x = *(unsigned*)&h0; pk.y = *(unsigned*)&h1;
        *(uint2*)dst = pk;
    }

    const int wid = tid >> 5, lane = tid & 31;
    const int wm = (wid & 3) * 32;
    const int wn = (wid >> 2) * 32;

#pragma unroll 1
    for (int stage = 0; stage < 8; stage++) {
        const int z = stage >> 2;
        const int nb = stage & 3;
        const __half* W   = z ? g_whr : g_whl;
        const float* bias = z ? br : bl;
        __half* out       = z ? g_xr : g_xl;
        const int bn = nb * 64;

        __syncthreads();
#pragma unroll
        for (int it = 0; it < 4; it++) {
            int q = it * 256 + tid;
            int row = q >> 3, cc = q & 7;
            uint4 v = *(const uint4*)&W[row * HC + bn + cc * 8];
            *(uint4*)&sB[row * 64 + ((cc ^ (row & 7)) << 3)] = v;
        }
        __syncthreads();

        float acc[2][4][4];
#pragma unroll
        for (int i = 0; i < 2; i++)
#pragma unroll
            for (int j = 0; j < 4; j++)
#pragma unroll
                for (int k = 0; k < 4; k++) acc[i][j][k] = 0.f;

#pragma unroll
        for (int ks = 0; ks < 8; ks++) {
            const int k0 = ks * 16;
            unsigned a[2][4], b[4][2];
#pragma unroll
            for (int am = 0; am < 2; am++) {
                int row = wm + am * 16 + (lane & 15);
                int cc = (k0 >> 3) + (lane >> 4);
                unsigned addr = smem_u32(&sA[row * 128 + ((cc ^ (row & 7)) << 3)]);
                ldm_x4(a[am][0], a[am][1], a[am][2], a[am][3], addr);
            }
#pragma unroll
            for (int bt = 0; bt < 2; bt++) {
                int row = k0 + (lane & 15);
                int cc = ((wn + bt * 16) >> 3) + (lane >> 4);
                unsigned addr = smem_u32(&sB[row * 64 + ((cc ^ (row & 7)) << 3)]);
                unsigned r0, r1, r2, r3;
                ldm_x4_t(r0, r1, r2, r3, addr);
                b[bt * 2 + 0][0] = r0; b[bt * 2 + 0][1] = r1;
                b[bt * 2 + 1][0] = r2; b[bt * 2 + 1][1] = r3;
            }
#pragma unroll
            for (int am = 0; am < 2; am++)
#pragma unroll
                for (int bt = 0; bt < 4; bt++) mma16816(acc[am][bt], a[am], b[bt]);
        }

#pragma unroll
        for (int am = 0; am < 2; am++) {
            int row0 = bm + wm + am * 16 + (lane >> 2);
#pragma unroll
            for (int bt = 0; bt < 4; bt++) {
                int col = bn + wn + bt * 8 + (lane & 3) * 2;
                float b0 = bias[col], b1 = bias[col + 1];
                if (row0 < NN)
                    *(__half2*)&out[row0 * HC + col] =
                        __floats2half2_rn(acc[am][bt][0] + b0, acc[am][bt][1] + b1);
                if (row0 + 8 < NN)
                    *(__half2*)&out[(row0 + 8) * HC + col] =
                        __floats2half2_rn(acc[am][bt][2] + b0, acc[am][bt][3] + b1);
            }
        }
    }
}

// ---------------- L3: fused attention + aggregate + pool (half2 math) ----------
__global__ __launch_bounds__(256, 6) void k_node(const float* __restrict__ att,
                                                 const float* __restrict__ bgnn,
                                                 const int* __restrict__ batch) {
    const int lane = threadIdx.x & 31;
    int w = (blockIdx.x * blockDim.x + threadIdx.x) >> 5;
    const int nw = (gridDim.x * blockDim.x) >> 5;

    __half2 at2[4];
    {
        const float4 a0 = *(const float4*)&att[lane * 8 + 0];
        const float4 a1 = *(const float4*)&att[lane * 8 + 4];
        at2[0] = __floats2half2_rn(a0.x, a0.y);
        at2[1] = __floats2half2_rn(a0.z, a0.w);
        at2[2] = __floats2half2_rn(a1.x, a1.y);
        at2[3] = __floats2half2_rn(a1.z, a1.w);
    }
    const __half2 C02 = __float2half2_rn(0.2f);

    for (int n = w; n < NN; n += nw) {
        __half2 r2[4];
        {
            uint4 ur = *(const uint4*)&g_xr[n * HC + lane * 8];
            const __half2* rh = (const __half2*)&ur;
            r2[0] = rh[0]; r2[1] = rh[1]; r2[2] = rh[2]; r2[3] = rh[3];
        }

        __half2 acc2[4];
        acc2[0] = __float2half2_rn(0.f);
        acc2[1] = acc2[0]; acc2[2] = acc2[0]; acc2[3] = acc2[0];
        float D = 0.f;

        auto doedge = [&](uint4 ul) {
            const __half2* lh = (const __half2*)&ul;
            __half2 ps = __float2half2_rn(0.f);
#pragma unroll
            for (int i = 0; i < 4; i++) {
                __half2 z = __hadd2(lh[i], r2[i]);
                __half2 lk = __hmax2(z, __hmul2(z, C02));
                ps = __hfma2(lk, at2[i], ps);
            }
            float2 pf = __half22float2(ps);
            float p = pf.x + pf.y;
            p += __shfl_xor_sync(0xffffffffu, p, 4);
            p += __shfl_xor_sync(0xffffffffu, p, 2);
            p += __shfl_xor_sync(0xffffffffu, p, 1);
            const float a = __expf(p - 6.0f);   // constant shift cancels in softmax
            D += a;
            const __half2 a2 = __float2half2_rn(a);
#pragma unroll
            for (int i = 0; i < 4; i++) acc2[i] = __hfma2(a2, lh[i], acc2[i]);
        };

        doedge(*(const uint4*)&g_xl[n * HC + lane * 8]);   // self loop

        const int beg = g_off[n], end = g_off[n + 1];
        int e = beg;
        const int end4 = beg + ((end - beg) & ~3);
        for (; e < end4; e += 4) {
            const int s0 = g_csrc[e], s1 = g_csrc[e + 1];
            const int s2 = g_csrc[e + 2], s3 = g_csrc[e + 3];
            uint4 u0 = *(const uint4*)&g_xl[s0 * HC + lane * 8];
            uint4 u1 = *(const uint4*)&g_xl[s1 * HC + lane * 8];
            uint4 u2 = *(const uint4*)&g_xl[s2 * HC + lane * 8];
            uint4 u3 = *(const uint4*)&g_xl[s3 * HC + lane * 8];
            doedge(u0); doedge(u1); doedge(u2); doedge(u3);
        }
        for (; e < end; e++) {
            const int s = g_csrc[e];
            doedge(*(const uint4*)&g_xl[s * HC + lane * 8]);
        }

        const float inv = 1.f / (D + 1e-16f);
        float v[8];
#pragma unroll
        for (int i = 0; i < 4; i++) {
            float2 af = __half22float2(acc2[i]);
            float t0 = af.x * inv, t1 = af.y * inv;
            t0 += __shfl_xor_sync(0xffffffffu, t0, 8);
            t0 += __shfl_xor_sync(0xffffffffu, t0, 16);
            t1 += __shfl_xor_sync(0xffffffffu, t1, 8);
            t1 += __shfl_xor_sync(0xffffffffu, t1, 16);
            v[2 * i] = t0; v[2 * i + 1] = t1;
        }

        if (lane < 8) {
            const int g = batch[n];
            if (lane == 0) atomicAdd(&g_cnt[g], 1);
#pragma unroll
            for (int j = 0; j < 8; j++) {
                const int c = lane * 8 + j;
                float val = fmaf(0.25f, v[j], bgnn[c]);
                val = fmaxf(val, 0.01f * val);
                atomicAdd(&g_pool[g * CC + c], val);
            }
        }
    }
}

// ---------------- L4: final FC (4 graphs x 128-col halves per block) ------------
__global__ __launch_bounds__(256) void k_fc(const float* __restrict__ hy,
                                            const float* __restrict__ Wfc,
                                            const float* __restrict__ bfc,
                                            float* __restrict__ out) {
    const int gb = (blockIdx.x >> 1) * FC_GPB;   // graph group
    const int ch = blockIdx.x & 1;               // column half
    const int j = threadIdx.x;
    const int col = ch * 128 + (j & 127);
    const int gp = j >> 7;                       // 0/1: which graph pair
    __shared__ float sh[FC_GPB][DENC_ + CC];

#pragma unroll
    for (int gi = 0; gi < FC_GPB; gi++) {
        const int g = gb + gi;
        sh[gi][j] = hy[g * DENC_ + j];
        if (j < CC) {
            int c = g_cnt[g];
            float cn = c > 0 ? (float)c : 1.f;
            sh[gi][DENC_ + j] = g_pool[g * CC + j] / cn;
        }
    }
    __syncthreads();

    // cleanup for next replay (disjoint from anything read here)
    for (int t = blockIdx.x * 256 + j; t < NN; t += FC_BLOCKS * 256) g_deg[t] = 0;
    if (blockIdx.x == 0 && j == 0) g_done = 0u;

    float acc0 = bfc[col], acc1 = acc0;
    const float* s0 = sh[gp * 2 + 0];
    const float* s1 = sh[gp * 2 + 1];
#pragma unroll 8
    for (int k = 0; k < DENC_ + CC; k++) {
        const float wv = Wfc[k * DENC_ + col];
        acc0 = fmaf(s0[k], wv, acc0);
        acc1 = fmaf(s1[k], wv, acc1);
    }
    out[(gb + gp * 2 + 0) * DENC_ + col] = acc0;
    out[(gb + gp * 2 + 1) * DENC_ + col] = acc1;
}

// ---------------- launch ----------------
extern "C" void kernel_launch(void* const* d_in, const int* in_sizes, int n_in,
                              void* d_out, int out_size) {
    const float* hy   = (const float*)d_in[0];
    const float* x    = (const float*)d_in[1];
    const int*   ei   = (const int*)d_in[2];
    const int*   batch= (const int*)d_in[3];
    const float* Wl   = (const float*)d_in[4];
    const float* bl   = (const float*)d_in[5];
    const float* Wr   = (const float*)d_in[6];
    const float* br   = (const float*)d_in[7];
    const float* att  = (const float*)d_in[8];
    const float* bgnn = (const float*)d_in[9];
    const float* Wfc  = (const float*)d_in[10];
    const float* bfc  = (const float*)d_in[11];
    float* out = (float*)d_out;

    k_pre<<<PRE_BLOCKS, 1024>>>(Wl, Wr, ei);                   // #1
    k_mid<<<SCAT_BLOCKS + MTILES, 256>>>(x, bl, br, ei);       // #2
    k_node<<<(NN + 7) / 8, 256>>>(att, bgnn, batch);           // #3
    k_fc<<<FC_BLOCKS, 256>>>(hy, Wfc, bfc, out);               // #4 (profiled)
}

// round 12
// speedup vs baseline: 1.2718x; 1.0069x over previous
#include <cuda_runtime.h>
#include <cuda_fp16.h>
#include <math.h>
#include <limits.h>

#define NN   50000
#define EE   800000
#define GG   512
#define HH   4
#define CC   64
#define HC   256      // H*C
#define DIN_ 128
#define DENC_ 256

#define MTILES 391          // (NN+127)/128
#define SCAT_BLOCKS 3125    // (EE+255)/256
#define PRE_BLOCKS 512
#define FC_GPB 4            // graphs per k_fc block
#define FC_BLOCKS ((GG / FC_GPB) * 2)   // 256: x2 column halves
#define KD (DENC_ + CC)     // 320
#define KHALF (KD / 2)      // 160

// ---------------- scratch (static device arrays; no allocation) ----------------
// INVARIANT (replay-safe): g_deg and g_done are zero at the start of every
// kernel_launch (zero-init initially; k_fc restores them at the end).
// g_pool/g_cnt are zeroed by k_pre at the START of each launch.
__device__ __half g_xl[NN * HC];     // 25.6 MB (fp16 node features, source)
__device__ __half g_xr[NN * HC];     // 25.6 MB (fp16 node features, target)
__device__ __half g_whl[DIN_ * HC];  // fp16 weights
__device__ __half g_whr[DIN_ * HC];
__device__ int   g_deg[NN];
__device__ int   g_off[NN + 1];
__device__ int   g_woff[NN];
__device__ int   g_csrc[EE];
__device__ float g_pool[GG * CC];
__device__ int   g_cnt[GG];
__device__ unsigned g_done;

// ---------------- mma helpers ----------------
__device__ __forceinline__ unsigned smem_u32(const void* p) {
    return (unsigned)__cvta_generic_to_shared(p);
}
__device__ __forceinline__ void ldm_x4(unsigned& r0, unsigned& r1, unsigned& r2,
                                       unsigned& r3, unsigned addr) {
    asm volatile("ldmatrix.sync.aligned.m8n8.x4.shared.b16 {%0,%1,%2,%3}, [%4];"
                 : "=r"(r0), "=r"(r1), "=r"(r2), "=r"(r3) : "r"(addr));
}
__device__ __forceinline__ void ldm_x4_t(unsigned& r0, unsigned& r1, unsigned& r2,
                                         unsigned& r3, unsigned addr) {
    asm volatile("ldmatrix.sync.aligned.m8n8.x4.trans.shared.b16 {%0,%1,%2,%3}, [%4];"
                 : "=r"(r0), "=r"(r1), "=r"(r2), "=r"(r3) : "r"(addr));
}
__device__ __forceinline__ void mma16816(float* d, const unsigned* a, const unsigned* b) {
    asm volatile(
        "mma.sync.aligned.m16n8k16.row.col.f32.f16.f16.f32 "
        "{%0,%1,%2,%3}, {%4,%5,%6,%7}, {%8,%9}, {%0,%1,%2,%3};"
        : "+f"(d[0]), "+f"(d[1]), "+f"(d[2]), "+f"(d[3])
        : "r"(a[0]), "r"(a[1]), "r"(a[2]), "r"(a[3]), "r"(b[0]), "r"(b[1]));
}

// ---------------- L1: weight convert + pool-zero + histogram + scan ------------
__global__ __launch_bounds__(1024) void k_pre(const float* __restrict__ Wl,
                                              const float* __restrict__ Wr,
                                              const int* __restrict__ ei) {
    const int i = blockIdx.x * 1024 + threadIdx.x;
    const int stride = gridDim.x * 1024;

    for (int j = i; j < DIN_ * HC / 2; j += stride) {
        float2 a = ((const float2*)Wl)[j];
        float2 b = ((const float2*)Wr)[j];
        ((__half2*)g_whl)[j] = __floats2half2_rn(a.x, a.y);
        ((__half2*)g_whr)[j] = __floats2half2_rn(b.x, b.y);
    }
    for (int j = i; j < GG * CC; j += stride) g_pool[j] = 0.f;
    for (int j = i; j < GG; j += stride) g_cnt[j] = 0;
    for (int t = i; t < EE; t += stride) atomicAdd(&g_deg[ei[EE + t]], 1);

    // last block performs the exclusive scan
    __threadfence();
    __syncthreads();
    __shared__ bool s_last;
    if (threadIdx.x == 0) {
        unsigned prev = atomicAdd(&g_done, 1u);
        s_last = (prev == (unsigned)(gridDim.x - 1));
    }
    __syncthreads();
    if (!s_last) return;
    __threadfence();

    __shared__ int warpsum[32];
    const int tid = threadIdx.x;
    const int per = (NN + 1023) / 1024;   // 49
    const int base = tid * per;
    int sum = 0;
    for (int k = 0; k < per; k++) {
        int idx = base + k;
        if (idx < NN) sum += g_deg[idx];
    }
    const int lane = tid & 31, wid = tid >> 5;
    int v = sum;
#pragma unroll
    for (int off = 1; off < 32; off <<= 1) {
        int u = __shfl_up_sync(0xffffffffu, v, off);
        if (lane >= off) v += u;
    }
    if (lane == 31) warpsum[wid] = v;
    __syncthreads();
    if (wid == 0) {
        int wv = warpsum[lane];
#pragma unroll
        for (int off = 1; off < 32; off <<= 1) {
            int u = __shfl_up_sync(0xffffffffu, wv, off);
            if (lane >= off) wv += u;
        }
        warpsum[lane] = wv;
    }
    __syncthreads();
    int excl = v - sum + (wid > 0 ? warpsum[wid - 1] : 0);
    int run = excl;
    for (int k = 0; k < per; k++) {
        int idx = base + k;
        if (idx < NN) {
            int c = g_deg[idx];
            g_off[idx] = run;
            g_woff[idx] = run;
            run += c;
        }
    }
    if (tid == 1023) g_off[NN] = run;
}

// ---------------- L2: fused CSR-scatter + tensor-core GEMM (A loaded once) ------
__global__ __launch_bounds__(256) void k_mid(const float* __restrict__ x,
                                             const float* __restrict__ bl,
                                             const float* __restrict__ br,
                                             const int* __restrict__ ei) {
    __shared__ __half sA[128 * 128];  // 32 KB
    __shared__ __half sB[128 * 64];   // 16 KB

    const int tid = threadIdx.x;
    int fb = blockIdx.x;

    if (fb < SCAT_BLOCKS) {           // ---- scatter part ----
        int t = fb * 256 + tid;
        if (t < EE) {
            int dst = ei[EE + t];
            int pos = atomicAdd(&g_woff[dst], 1);
            g_csrc[pos] = ei[t];
        }
        return;
    }
    const int mb = fb - SCAT_BLOCKS;  // ---- gemm part ----
    const int bm = mb * 128;

#pragma unroll
    for (int it = 0; it < 16; it++) {
        int q = it * 256 + tid;
        int row = q >> 5, c4 = q & 31;
        int gm = bm + row;
        float4 v = make_float4(0.f, 0.f, 0.f, 0.f);
        if (gm < NN) v = *(const float4*)&x[gm * DIN_ + c4 * 4];
        __half2 h0 = __floats2half2_rn(v.x, v.y);
        __half2 h1 = __floats2half2_rn(v.z, v.w);
        int cc = c4 >> 1, sub = (c4 & 1) << 2;
        __half* dst = &sA[row * 128 + ((cc ^ (row & 7)) << 3) + sub];
        uint2 pk;
        pk.x = *(unsigned*)&h0; pk.y = *(unsigned*)&h1;
        *(uint2*)dst = pk;
    }

    const int wid = tid >> 5, lane = tid & 31;
    const int wm = (wid & 3) * 32;
    const int wn = (wid >> 2) * 32;

#pragma unroll 1
    for (int stage = 0; stage < 8; stage++) {
        const int z = stage >> 2;
        const int nb = stage & 3;
        const __half* W   = z ? g_whr : g_whl;
        const float* bias = z ? br : bl;
        __half* out       = z ? g_xr : g_xl;
        const int bn = nb * 64;

        __syncthreads();
#pragma unroll
        for (int it = 0; it < 4; it++) {
            int q = it * 256 + tid;
            int row = q >> 3, cc = q & 7;
            uint4 v = *(const uint4*)&W[row * HC + bn + cc * 8];
            *(uint4*)&sB[row * 64 + ((cc ^ (row & 7)) << 3)] = v;
        }
        __syncthreads();

        float acc[2][4][4];
#pragma unroll
        for (int i = 0; i < 2; i++)
#pragma unroll
            for (int j = 0; j < 4; j++)
#pragma unroll
                for (int k = 0; k < 4; k++) acc[i][j][k] = 0.f;

#pragma unroll
        for (int ks = 0; ks < 8; ks++) {
            const int k0 = ks * 16;
            unsigned a[2][4], b[4][2];
#pragma unroll
            for (int am = 0; am < 2; am++) {
                int row = wm + am * 16 + (lane & 15);
                int cc = (k0 >> 3) + (lane >> 4);
                unsigned addr = smem_u32(&sA[row * 128 + ((cc ^ (row & 7)) << 3)]);
                ldm_x4(a[am][0], a[am][1], a[am][2], a[am][3], addr);
            }
#pragma unroll
            for (int bt = 0; bt < 2; bt++) {
                int row = k0 + (lane & 15);
                int cc = ((wn + bt * 16) >> 3) + (lane >> 4);
                unsigned addr = smem_u32(&sB[row * 64 + ((cc ^ (row & 7)) << 3)]);
                unsigned r0, r1, r2, r3;
                ldm_x4_t(r0, r1, r2, r3, addr);
                b[bt * 2 + 0][0] = r0; b[bt * 2 + 0][1] = r1;
                b[bt * 2 + 1][0] = r2; b[bt * 2 + 1][1] = r3;
            }
#pragma unroll
            for (int am = 0; am < 2; am++)
#pragma unroll
                for (int bt = 0; bt < 4; bt++) mma16816(acc[am][bt], a[am], b[bt]);
        }

#pragma unroll
        for (int am = 0; am < 2; am++) {
            int row0 = bm + wm + am * 16 + (lane >> 2);
#pragma unroll
            for (int bt = 0; bt < 4; bt++) {
                int col = bn + wn + bt * 8 + (lane & 3) * 2;
                float b0 = bias[col], b1 = bias[col + 1];
                if (row0 < NN)
                    *(__half2*)&out[row0 * HC + col] =
                        __floats2half2_rn(acc[am][bt][0] + b0, acc[am][bt][1] + b1);
                if (row0 + 8 < NN)
                    *(__half2*)&out[(row0 + 8) * HC + col] =
                        __floats2half2_rn(acc[am][bt][2] + b0, acc[am][bt][3] + b1);
            }
        }
    }
}

// ---------------- L3: fused attention + aggregate + pool (half2 math) ----------
__global__ __launch_bounds__(256, 6) void k_node(const float* __restrict__ att,
                                                 const float* __restrict__ bgnn,
                                                 const int* __restrict__ batch) {
    const int lane = threadIdx.x & 31;
    int w = (blockIdx.x * blockDim.x + threadIdx.x) >> 5;
    const int nw = (gridDim.x * blockDim.x) >> 5;

    __half2 at2[4];
    {
        const float4 a0 = *(const float4*)&att[lane * 8 + 0];
        const float4 a1 = *(const float4*)&att[lane * 8 + 4];
        at2[0] = __floats2half2_rn(a0.x, a0.y);
        at2[1] = __floats2half2_rn(a0.z, a0.w);
        at2[2] = __floats2half2_rn(a1.x, a1.y);
        at2[3] = __floats2half2_rn(a1.z, a1.w);
    }
    const __half2 C02 = __float2half2_rn(0.2f);

    for (int n = w; n < NN; n += nw) {
        __half2 r2[4];
        {
            uint4 ur = *(const uint4*)&g_xr[n * HC + lane * 8];
            const __half2* rh = (const __half2*)&ur;
            r2[0] = rh[0]; r2[1] = rh[1]; r2[2] = rh[2]; r2[3] = rh[3];
        }

        __half2 acc2[4];
        acc2[0] = __float2half2_rn(0.f);
        acc2[1] = acc2[0]; acc2[2] = acc2[0]; acc2[3] = acc2[0];
        float D = 0.f;

        auto doedge = [&](uint4 ul) {
            const __half2* lh = (const __half2*)&ul;
            __half2 ps = __float2half2_rn(0.f);
#pragma unroll
            for (int i = 0; i < 4; i++) {
                __half2 z = __hadd2(lh[i], r2[i]);
                __half2 lk = __hmax2(z, __hmul2(z, C02));
                ps = __hfma2(lk, at2[i], ps);
            }
            float2 pf = __half22float2(ps);
            float p = pf.x + pf.y;
            p += __shfl_xor_sync(0xffffffffu, p, 4);
            p += __shfl_xor_sync(0xffffffffu, p, 2);
            p += __shfl_xor_sync(0xffffffffu, p, 1);
            const float a = __expf(p - 6.0f);   // constant shift cancels in softmax
            D += a;
            const __half2 a2 = __float2half2_rn(a);
#pragma unroll
            for (int i = 0; i < 4; i++) acc2[i] = __hfma2(a2, lh[i], acc2[i]);
        };

        doedge(*(const uint4*)&g_xl[n * HC + lane * 8]);   // self loop

        const int beg = g_off[n], end = g_off[n + 1];
        int e = beg;
        const int end4 = beg + ((end - beg) & ~3);
        for (; e < end4; e += 4) {
            const int s0 = g_csrc[e], s1 = g_csrc[e + 1];
            const int s2 = g_csrc[e + 2], s3 = g_csrc[e + 3];
            uint4 u0 = *(const uint4*)&g_xl[s0 * HC + lane * 8];
            uint4 u1 = *(const uint4*)&g_xl[s1 * HC + lane * 8];
            uint4 u2 = *(const uint4*)&g_xl[s2 * HC + lane * 8];
            uint4 u3 = *(const uint4*)&g_xl[s3 * HC + lane * 8];
            doedge(u0); doedge(u1); doedge(u2); doedge(u3);
        }
        for (; e < end; e++) {
            const int s = g_csrc[e];
            doedge(*(const uint4*)&g_xl[s * HC + lane * 8]);
        }

        const float inv = 1.f / (D + 1e-16f);
        float v[8];
#pragma unroll
        for (int i = 0; i < 4; i++) {
            float2 af = __half22float2(acc2[i]);
            float t0 = af.x * inv, t1 = af.y * inv;
            t0 += __shfl_xor_sync(0xffffffffu, t0, 8);
            t0 += __shfl_xor_sync(0xffffffffu, t0, 16);
            t1 += __shfl_xor_sync(0xffffffffu, t1, 8);
            t1 += __shfl_xor_sync(0xffffffffu, t1, 16);
            v[2 * i] = t0; v[2 * i + 1] = t1;
        }

        if (lane < 8) {
            const int g = batch[n];
            if (lane == 0) atomicAdd(&g_cnt[g], 1);
#pragma unroll
            for (int j = 0; j < 8; j++) {
                const int c = lane * 8 + j;
                float val = fmaf(0.25f, v[j], bgnn[c]);
                val = fmaxf(val, 0.01f * val);
                atomicAdd(&g_pool[g * CC + c], val);
            }
        }
    }
}

// ---------------- L4: final FC (4 graphs x 128 cols x 2 k-halves) ---------------
__global__ __launch_bounds__(256) void k_fc(const float* __restrict__ hy,
                                            const float* __restrict__ Wfc,
                                            const float* __restrict__ bfc,
                                            float* __restrict__ out) {
    const int gb = (blockIdx.x >> 1) * FC_GPB;   // graph group
    const int ch = blockIdx.x & 1;               // column half
    const int j = threadIdx.x;
    const int cj = j & 127;
    const int col = ch * 128 + cj;
    const int kh = j >> 7;                       // k half: 0/1
    __shared__ float sh[FC_GPB][KD];
    __shared__ float red[FC_GPB][128];

#pragma unroll
    for (int gi = 0; gi < FC_GPB; gi++) {
        const int g = gb + gi;
        sh[gi][j] = hy[g * DENC_ + j];
        if (j < CC) {
            int c = g_cnt[g];
            float cn = c > 0 ? (float)c : 1.f;
            sh[gi][DENC_ + j] = g_pool[g * CC + j] / cn;
        }
    }
    __syncthreads();

    // cleanup for next replay (disjoint from anything read here)
    for (int t = blockIdx.x * 256 + j; t < NN; t += FC_BLOCKS * 256) g_deg[t] = 0;
    if (blockIdx.x == 0 && j == 0) g_done = 0u;

    float acc[FC_GPB];
#pragma unroll
    for (int gi = 0; gi < FC_GPB; gi++) acc[gi] = (kh == 0) ? bfc[col] : 0.f;

    const int k0 = kh * KHALF;
#pragma unroll 8
    for (int k = k0; k < k0 + KHALF; k++) {
        const float wv = Wfc[k * DENC_ + col];
#pragma unroll
        for (int gi = 0; gi < FC_GPB; gi++) acc[gi] = fmaf(sh[gi][k], wv, acc[gi]);
    }

    if (kh == 1) {
#pragma unroll
        for (int gi = 0; gi < FC_GPB; gi++) red[gi][cj] = acc[gi];
    }
    __syncthreads();
    if (kh == 0) {
#pragma unroll
        for (int gi = 0; gi < FC_GPB; gi++)
            out[(gb + gi) * DENC_ + col] = acc[gi] + red[gi][cj];
    }
}

// ---------------- launch ----------------
extern "C" void kernel_launch(void* const* d_in, const int* in_sizes, int n_in,
                              void* d_out, int out_size) {
    const float* hy   = (const float*)d_in[0];
    const float* x    = (const float*)d_in[1];
    const int*   ei   = (const int*)d_in[2];
    const int*   batch= (const int*)d_in[3];
    const float* Wl   = (const float*)d_in[4];
    const float* bl   = (const float*)d_in[5];
    const float* Wr   = (const float*)d_in[6];
    const float* br   = (const float*)d_in[7];
    const float* att  = (const float*)d_in[8];
    const float* bgnn = (const float*)d_in[9];
    const float* Wfc  = (const float*)d_in[10];
    const float* bfc  = (const float*)d_in[11];
    float* out = (float*)d_out;

    k_pre<<<PRE_BLOCKS, 1024>>>(Wl, Wr, ei);                   // #1
    k_mid<<<SCAT_BLOCKS + MTILES, 256>>>(x, bl, br, ei);       // #2
    k_node<<<(NN + 7) / 8, 256>>>(att, bgnn, batch);           // #3
    k_fc<<<FC_BLOCKS, 256>>>(hy, Wfc, bfc, out);               // #4 (profiled)
}

// round 13
// speedup vs baseline: 1.2951x; 1.0183x over previous
#include <cuda_runtime.h>
#include <cuda_fp16.h>
#include <math.h>
#include <limits.h>

#define NN   50000
#define EE   800000
#define GG   512
#define HH   4
#define CC   64
#define HC   256      // H*C
#define DIN_ 128
#define DENC_ 256

#define MTILES 391          // (NN+127)/128
#define SCAT_BLOCKS 3125    // (EE+255)/256
#define PRE_BLOCKS 512
#define FC_GPB 4            // graphs per k_fc block
#define FC_BLOCKS ((GG / FC_GPB) * 2)   // 256
#define KD (DENC_ + CC)     // 320
#define KHALF (KD / 2)      // 160

// ---------------- scratch (static device arrays; no allocation) ----------------
// INVARIANT (replay-safe): g_deg and g_done are zero at the start of every
// kernel_launch (zero-init initially; k_fc restores them at the end).
// g_pool/g_cnt are zeroed by k_pre at the START of each launch.
__device__ __half g_xl[NN * HC];     // 25.6 MB
__device__ __half g_xr[NN * HC];     // 25.6 MB
__device__ __half g_whl[DIN_ * HC];
__device__ __half g_whr[DIN_ * HC];
__device__ int   g_deg[NN];
__device__ int   g_off[NN + 1];
__device__ int   g_woff[NN];
__device__ int   g_csrc[EE];
__device__ float g_pool[GG * CC];
__device__ int   g_cnt[GG];
__device__ unsigned g_done;

// ---------------- mma helpers ----------------
__device__ __forceinline__ unsigned smem_u32(const void* p) {
    return (unsigned)__cvta_generic_to_shared(p);
}
__device__ __forceinline__ void ldm_x4(unsigned& r0, unsigned& r1, unsigned& r2,
                                       unsigned& r3, unsigned addr) {
    asm volatile("ldmatrix.sync.aligned.m8n8.x4.shared.b16 {%0,%1,%2,%3}, [%4];"
                 : "=r"(r0), "=r"(r1), "=r"(r2), "=r"(r3) : "r"(addr));
}
__device__ __forceinline__ void ldm_x4_t(unsigned& r0, unsigned& r1, unsigned& r2,
                                         unsigned& r3, unsigned addr) {
    asm volatile("ldmatrix.sync.aligned.m8n8.x4.trans.shared.b16 {%0,%1,%2,%3}, [%4];"
                 : "=r"(r0), "=r"(r1), "=r"(r2), "=r"(r3) : "r"(addr));
}
__device__ __forceinline__ void mma16816(float* d, const unsigned* a, const unsigned* b) {
    asm volatile(
        "mma.sync.aligned.m16n8k16.row.col.f32.f16.f16.f32 "
        "{%0,%1,%2,%3}, {%4,%5,%6,%7}, {%8,%9}, {%0,%1,%2,%3};"
        : "+f"(d[0]), "+f"(d[1]), "+f"(d[2]), "+f"(d[3])
        : "r"(a[0]), "r"(a[1]), "r"(a[2]), "r"(a[3]), "r"(b[0]), "r"(b[1]));
}

// ---------------- L1: weight convert + pool-zero + histogram + scan ------------
__global__ __launch_bounds__(1024) void k_pre(const float* __restrict__ Wl,
                                              const float* __restrict__ Wr,
                                              const int* __restrict__ ei) {
    const int i = blockIdx.x * 1024 + threadIdx.x;
    const int stride = gridDim.x * 1024;

    for (int j = i; j < DIN_ * HC / 2; j += stride) {
        float2 a = ((const float2*)Wl)[j];
        float2 b = ((const float2*)Wr)[j];
        ((__half2*)g_whl)[j] = __floats2half2_rn(a.x, a.y);
        ((__half2*)g_whr)[j] = __floats2half2_rn(b.x, b.y);
    }
    for (int j = i; j < GG * CC; j += stride) g_pool[j] = 0.f;
    for (int j = i; j < GG; j += stride) g_cnt[j] = 0;
    for (int t = i; t < EE; t += stride) atomicAdd(&g_deg[ei[EE + t]], 1);

    __threadfence();
    __syncthreads();
    __shared__ bool s_last;
    if (threadIdx.x == 0) {
        unsigned prev = atomicAdd(&g_done, 1u);
        s_last = (prev == (unsigned)(gridDim.x - 1));
    }
    __syncthreads();
    if (!s_last) return;
    __threadfence();

    __shared__ int warpsum[32];
    const int tid = threadIdx.x;
    const int per = (NN + 1023) / 1024;   // 49
    const int base = tid * per;
    int sum = 0;
    for (int k = 0; k < per; k++) {
        int idx = base + k;
        if (idx < NN) sum += g_deg[idx];
    }
    const int lane = tid & 31, wid = tid >> 5;
    int v = sum;
#pragma unroll
    for (int off = 1; off < 32; off <<= 1) {
        int u = __shfl_up_sync(0xffffffffu, v, off);
        if (lane >= off) v += u;
    }
    if (lane == 31) warpsum[wid] = v;
    __syncthreads();
    if (wid == 0) {
        int wv = warpsum[lane];
#pragma unroll
        for (int off = 1; off < 32; off <<= 1) {
            int u = __shfl_up_sync(0xffffffffu, wv, off);
            if (lane >= off) wv += u;
        }
        warpsum[lane] = wv;
    }
    __syncthreads();
    int excl = v - sum + (wid > 0 ? warpsum[wid - 1] : 0);
    int run = excl;
    for (int k = 0; k < per; k++) {
        int idx = base + k;
        if (idx < NN) {
            int c = g_deg[idx];
            g_off[idx] = run;
            g_woff[idx] = run;
            run += c;
        }
    }
    if (tid == 1023) g_off[NN] = run;
}

// ---------------- L2: fused CSR-scatter + GEMM (A once, B double-buffered) ------
__global__ __launch_bounds__(256) void k_mid(const float* __restrict__ x,
                                             const float* __restrict__ bl,
                                             const float* __restrict__ br,
                                             const int* __restrict__ ei) {
    __shared__ __half sA[128 * 128];     // 32 KB
    __shared__ __half sB[2][128 * 64];   // 32 KB (double buffer)

    const int tid = threadIdx.x;
    int fb = blockIdx.x;

    if (fb < SCAT_BLOCKS) {           // ---- scatter part ----
        int t = fb * 256 + tid;
        if (t < EE) {
            int dst = ei[EE + t];
            int pos = atomicAdd(&g_woff[dst], 1);
            g_csrc[pos] = ei[t];
        }
        return;
    }
    const int mb = fb - SCAT_BLOCKS;  // ---- gemm part ----
    const int bm = mb * 128;

    // A tile once: fp32 -> half, swizzled
#pragma unroll
    for (int it = 0; it < 16; it++) {
        int q = it * 256 + tid;
        int row = q >> 5, c4 = q & 31;
        int gm = bm + row;
        float4 v = make_float4(0.f, 0.f, 0.f, 0.f);
        if (gm < NN) v = *(const float4*)&x[gm * DIN_ + c4 * 4];
        __half2 h0 = __floats2half2_rn(v.x, v.y);
        __half2 h1 = __floats2half2_rn(v.z, v.w);
        int cc = c4 >> 1, sub = (c4 & 1) << 2;
        __half* dst = &sA[row * 128 + ((cc ^ (row & 7)) << 3) + sub];
        uint2 pk;
        pk.x = *(unsigned*)&h0; pk.y = *(unsigned*)&h1;
        *(uint2*)dst = pk;
    }
    // preload B of stage 0 (whl, bn=0)
    {
        const int row = tid >> 1, cc4 = (tid & 1) << 2;  // 2 uint4 per row-half
#pragma unroll
        for (int it = 0; it < 4; it++) {
            int q = it * 256 + tid;
            int r2_ = q >> 3, cc = q & 7;
            uint4 v = *(const uint4*)&g_whl[r2_ * HC + 0 + cc * 8];
            *(uint4*)&sB[0][r2_ * 64 + ((cc ^ (r2_ & 7)) << 3)] = v;
        }
        (void)row; (void)cc4;
    }
    __syncthreads();

    const int wid = tid >> 5, lane = tid & 31;
    const int wm = (wid & 3) * 32;
    const int wn = (wid >> 2) * 32;

#pragma unroll 1
    for (int stage = 0; stage < 8; stage++) {
        const int cur = stage & 1;
        const int z = stage >> 2;
        const int nb = stage & 3;
        const float* bias = z ? br : bl;
        __half* out       = z ? g_xr : g_xl;
        const int bn = nb * 64;

        // prefetch next stage's B into registers (overlaps with MMAs)
        uint4 vnext[4];
        int nrow[4], ncc[4];
        if (stage < 7) {
            const int ns = stage + 1;
            const __half* Wn = (ns >> 2) ? g_whr : g_whl;
            const int nbn = (ns & 3) * 64;
#pragma unroll
            for (int it = 0; it < 4; it++) {
                int q = it * 256 + tid;
                nrow[it] = q >> 3; ncc[it] = q & 7;
                vnext[it] = *(const uint4*)&Wn[nrow[it] * HC + nbn + ncc[it] * 8];
            }
        }

        float acc[2][4][4];
#pragma unroll
        for (int i = 0; i < 2; i++)
#pragma unroll
            for (int j = 0; j < 4; j++)
#pragma unroll
                for (int k = 0; k < 4; k++) acc[i][j][k] = 0.f;

#pragma unroll
        for (int ks = 0; ks < 8; ks++) {
            const int k0 = ks * 16;
            unsigned a[2][4], b[4][2];
#pragma unroll
            for (int am = 0; am < 2; am++) {
                int row = wm + am * 16 + (lane & 15);
                int cc = (k0 >> 3) + (lane >> 4);
                unsigned addr = smem_u32(&sA[row * 128 + ((cc ^ (row & 7)) << 3)]);
                ldm_x4(a[am][0], a[am][1], a[am][2], a[am][3], addr);
            }
#pragma unroll
            for (int bt = 0; bt < 2; bt++) {
                int row = k0 + (lane & 15);
                int cc = ((wn + bt * 16) >> 3) + (lane >> 4);
                unsigned addr = smem_u32(&sB[cur][row * 64 + ((cc ^ (row & 7)) << 3)]);
                unsigned r0, r1, r2, r3;
                ldm_x4_t(r0, r1, r2, r3, addr);
                b[bt * 2 + 0][0] = r0; b[bt * 2 + 0][1] = r1;
                b[bt * 2 + 1][0] = r2; b[bt * 2 + 1][1] = r3;
            }
#pragma unroll
            for (int am = 0; am < 2; am++)
#pragma unroll
                for (int bt = 0; bt < 4; bt++) mma16816(acc[am][bt], a[am], b[bt]);
        }

        // epilogue store
#pragma unroll
        for (int am = 0; am < 2; am++) {
            int row0 = bm + wm + am * 16 + (lane >> 2);
#pragma unroll
            for (int bt = 0; bt < 4; bt++) {
                int col = bn + wn + bt * 8 + (lane & 3) * 2;
                float b0 = bias[col], b1 = bias[col + 1];
                if (row0 < NN)
                    *(__half2*)&out[row0 * HC + col] =
                        __floats2half2_rn(acc[am][bt][0] + b0, acc[am][bt][1] + b1);
                if (row0 + 8 < NN)
                    *(__half2*)&out[(row0 + 8) * HC + col] =
                        __floats2half2_rn(acc[am][bt][2] + b0, acc[am][bt][3] + b1);
            }
        }

        if (stage < 7) {
#pragma unroll
            for (int it = 0; it < 4; it++)
                *(uint4*)&sB[1 - cur][nrow[it] * 64 + ((ncc[it] ^ (nrow[it] & 7)) << 3)] = vnext[it];
        }
        __syncthreads();
    }
}

// ---------------- L3: fused attention + aggregate + pool (paired edges) --------
__global__ __launch_bounds__(256, 6) void k_node(const float* __restrict__ att,
                                                 const float* __restrict__ bgnn,
                                                 const int* __restrict__ batch) {
    const int lane = threadIdx.x & 31;
    int w = (blockIdx.x * blockDim.x + threadIdx.x) >> 5;
    const int nw = (gridDim.x * blockDim.x) >> 5;

    __half2 at2[4];
    {
        const float4 a0 = *(const float4*)&att[lane * 8 + 0];
        const float4 a1 = *(const float4*)&att[lane * 8 + 4];
        at2[0] = __floats2half2_rn(a0.x, a0.y);
        at2[1] = __floats2half2_rn(a0.z, a0.w);
        at2[2] = __floats2half2_rn(a1.x, a1.y);
        at2[3] = __floats2half2_rn(a1.z, a1.w);
    }
    const __half2 C02 = __float2half2_rn(0.2f);

    for (int n = w; n < NN; n += nw) {
        __half2 r2[4];
        {
            uint4 ur = *(const uint4*)&g_xr[n * HC + lane * 8];
            const __half2* rh = (const __half2*)&ur;
            r2[0] = rh[0]; r2[1] = rh[1]; r2[2] = rh[2]; r2[3] = rh[3];
        }

        __half2 acc2[4];
        acc2[0] = __float2half2_rn(0.f);
        acc2[1] = acc2[0]; acc2[2] = acc2[0]; acc2[3] = acc2[0];
        float D = 0.f;

        // single edge (self loop / odd remainder)
        auto doedge1 = [&](uint4 ul) {
            const __half2* lh = (const __half2*)&ul;
            __half2 ps = __float2half2_rn(0.f);
#pragma unroll
            for (int i = 0; i < 4; i++) {
                __half2 z = __hadd2(lh[i], r2[i]);
                __half2 lk = __hmax2(z, __hmul2(z, C02));
                ps = __hfma2(lk, at2[i], ps);
            }
            float2 pf = __half22float2(ps);
            float p = pf.x + pf.y;
            p += __shfl_xor_sync(0xffffffffu, p, 4);
            p += __shfl_xor_sync(0xffffffffu, p, 2);
            p += __shfl_xor_sync(0xffffffffu, p, 1);
            const float a = __expf(p - 6.0f);
            D += a;
            const __half2 a2 = __float2half2_rn(a);
#pragma unroll
            for (int i = 0; i < 4; i++) acc2[i] = __hfma2(a2, lh[i], acc2[i]);
        };

        // pair of edges: one shuffle chain serves both (packed half2)
        auto doedge2 = [&](uint4 ul0, uint4 ul1) {
            const __half2* lh0 = (const __half2*)&ul0;
            const __half2* lh1 = (const __half2*)&ul1;
            __half2 ps0 = __float2half2_rn(0.f);
            __half2 ps1 = ps0;
#pragma unroll
            for (int i = 0; i < 4; i++) {
                __half2 z0 = __hadd2(lh0[i], r2[i]);
                __half2 z1 = __hadd2(lh1[i], r2[i]);
                ps0 = __hfma2(__hmax2(z0, __hmul2(z0, C02)), at2[i], ps0);
                ps1 = __hfma2(__hmax2(z1, __hmul2(z1, C02)), at2[i], ps1);
            }
            __half2 ph = __hadd2(__lows2half2(ps0, ps1), __highs2half2(ps0, ps1));
#pragma unroll
            for (int s = 4; s > 0; s >>= 1) {
                unsigned pu = __shfl_xor_sync(0xffffffffu,
                                              *(unsigned*)&ph, s);
                ph = __hadd2(ph, *(__half2*)&pu);
            }
            float2 pf = __half22float2(ph);
            float a0 = __expf(pf.x - 6.0f);
            float a1 = __expf(pf.y - 6.0f);
            D += a0 + a1;
            const __half2 ah0 = __float2half2_rn(a0);
            const __half2 ah1 = __float2half2_rn(a1);
#pragma unroll
            for (int i = 0; i < 4; i++) {
                acc2[i] = __hfma2(ah0, lh0[i], acc2[i]);
                acc2[i] = __hfma2(ah1, lh1[i], acc2[i]);
            }
        };

        doedge1(*(const uint4*)&g_xl[n * HC + lane * 8]);   // self loop

        const int beg = g_off[n], end = g_off[n + 1];
        int e = beg;
        for (; e + 1 < end; e += 2) {
            const int s0 = g_csrc[e], s1 = g_csrc[e + 1];
            uint4 u0 = *(const uint4*)&g_xl[s0 * HC + lane * 8];
            uint4 u1 = *(const uint4*)&g_xl[s1 * HC + lane * 8];
            doedge2(u0, u1);
        }
        if (e < end) {
            const int s = g_csrc[e];
            doedge1(*(const uint4*)&g_xl[s * HC + lane * 8]);
        }

        const float inv = 1.f / (D + 1e-16f);
        float v[8];
#pragma unroll
        for (int i = 0; i < 4; i++) {
            float2 af = __half22float2(acc2[i]);
            float t0 = af.x * inv, t1 = af.y * inv;
            t0 += __shfl_xor_sync(0xffffffffu, t0, 8);
            t0 += __shfl_xor_sync(0xffffffffu, t0, 16);
            t1 += __shfl_xor_sync(0xffffffffu, t1, 8);
            t1 += __shfl_xor_sync(0xffffffffu, t1, 16);
            v[2 * i] = t0; v[2 * i + 1] = t1;
        }

        if (lane < 8) {
            const int g = batch[n];
            if (lane == 0) atomicAdd(&g_cnt[g], 1);
#pragma unroll
            for (int j = 0; j < 8; j++) {
                const int c = lane * 8 + j;
                float val = fmaf(0.25f, v[j], bgnn[c]);
                val = fmaxf(val, 0.01f * val);
                atomicAdd(&g_pool[g * CC + c], val);
            }
        }
    }
}

// ---------------- L4: final FC (4 graphs x 128 cols x 2 k-halves) ---------------
__global__ __launch_bounds__(256) void k_fc(const float* __restrict__ hy,
                                            const float* __restrict__ Wfc,
                                            const float* __restrict__ bfc,
                                            float* __restrict__ out) {
    const int gb = (blockIdx.x >> 1) * FC_GPB;
    const int ch = blockIdx.x & 1;
    const int j = threadIdx.x;
    const int cj = j & 127;
    const int col = ch * 128 + cj;
    const int kh = j >> 7;
    __shared__ float sh[FC_GPB][KD];
    __shared__ float red[FC_GPB][128];

#pragma unroll
    for (int gi = 0; gi < FC_GPB; gi++) {
        const int g = gb + gi;
        sh[gi][j] = hy[g * DENC_ + j];
        if (j < CC) {
            int c = g_cnt[g];
            float cn = c > 0 ? (float)c : 1.f;
            sh[gi][DENC_ + j] = g_pool[g * CC + j] / cn;
        }
    }
    __syncthreads();

    for (int t = blockIdx.x * 256 + j; t < NN; t += FC_BLOCKS * 256) g_deg[t] = 0;
    if (blockIdx.x == 0 && j == 0) g_done = 0u;

    float acc[FC_GPB];
#pragma unroll
    for (int gi = 0; gi < FC_GPB; gi++) acc[gi] = (kh == 0) ? bfc[col] : 0.f;

    const int k0 = kh * KHALF;
#pragma unroll 8
    for (int k = k0; k < k0 + KHALF; k++) {
        const float wv = Wfc[k * DENC_ + col];
#pragma unroll
        for (int gi = 0; gi < FC_GPB; gi++) acc[gi] = fmaf(sh[gi][k], wv, acc[gi]);
    }

    if (kh == 1) {
#pragma unroll
        for (int gi = 0; gi < FC_GPB; gi++) red[gi][cj] = acc[gi];
    }
    __syncthreads();
    if (kh == 0) {
#pragma unroll
        for (int gi = 0; gi < FC_GPB; gi++)
            out[(gb + gi) * DENC_ + col] = acc[gi] + red[gi][cj];
    }
}

// ---------------- launch ----------------
extern "C" void kernel_launch(void* const* d_in, const int* in_sizes, int n_in,
                              void* d_out, int out_size) {
    const float* hy   = (const float*)d_in[0];
    const float* x    = (const float*)d_in[1];
    const int*   ei   = (const int*)d_in[2];
    const int*   batch= (const int*)d_in[3];
    const float* Wl   = (const float*)d_in[4];
    const float* bl   = (const float*)d_in[5];
    const float* Wr   = (const float*)d_in[6];
    const float* br   = (const float*)d_in[7];
    const float* att  = (const float*)d_in[8];
    const float* bgnn = (const float*)d_in[9];
    const float* Wfc  = (const float*)d_in[10];
    const float* bfc  = (const float*)d_in[11];
    float* out = (float*)d_out;

    k_pre<<<PRE_BLOCKS, 1024>>>(Wl, Wr, ei);                   // #1
    k_mid<<<SCAT_BLOCKS + MTILES, 256>>>(x, bl, br, ei);       // #2
    k_node<<<(NN + 7) / 8, 256>>>(att, bgnn, batch);           // #3
    k_fc<<<FC_BLOCKS, 256>>>(hy, Wfc, bfc, out);               // #4 (profiled)
}